// round 8
// baseline (speedup 1.0000x reference)
#include <cuda_runtime.h>
#include <math.h>
#include <stddef.h>

// ---------------------------------------------------------------------------
// GeometricCrossAttentionBlock — fp32 + f32x2 packed FMA + flash attention
//   streams: 0 = src (tokens 0..4095), 1 = tgt (tokens 4096..8191)
//   d_out doubles as the running residual buffer "cur" [8192][256]
// ---------------------------------------------------------------------------

#define TOKS   8192
#define DIMM   256
#define NSEQ   1024
#define NHEAD  8
#define HDIM   32
#define FFND   1024
#define ATT_SCALE 0.17677669529663687f   /* 32^-0.5 */

typedef unsigned long long u64;

// -------------------- f32x2 helpers (sm_103a packed fp32) ------------------
__device__ __forceinline__ u64 pack2(float x, float y) {
    u64 r; asm("mov.b64 %0, {%1, %2};" : "=l"(r) : "f"(x), "f"(y)); return r;
}
__device__ __forceinline__ void unpack2(u64 v, float& x, float& y) {
    asm("mov.b64 {%0, %1}, %2;" : "=f"(x), "=f"(y) : "l"(v));
}
__device__ __forceinline__ u64 fma2(u64 a, u64 b, u64 c) {
    u64 d; asm("fma.rn.f32x2 %0, %1, %2, %3;" : "=l"(d) : "l"(a), "l"(b), "l"(c)); return d;
}
__device__ __forceinline__ u64 mul2(u64 a, u64 b) {
    u64 d; asm("mul.rn.f32x2 %0, %1, %2;" : "=l"(d) : "l"(a), "l"(b)); return d;
}

// -------------------- device scratch (allocation-free rule) ----------------
__device__ float g_xn [TOKS * DIMM];            //  8 MB   LN output
__device__ float g_q  [TOKS * DIMM];            //  8 MB
__device__ float g_k  [TOKS * DIMM];            //  8 MB
__device__ float g_v  [TOKS * DIMM];            //  8 MB
__device__ float g_att[TOKS * DIMM];            //  8 MB   attention out (pre O-proj)
__device__ float g_h  [TOKS * FFND];            // 32 MB   FFN hidden

// ---------------------------------------------------------------------------
// LayerNorm over last dim (256). One block (256 thr) per row.
// ---------------------------------------------------------------------------
__global__ void __launch_bounds__(256) ln_kernel(
    const float* __restrict__ in, const float* __restrict__ g,
    const float* __restrict__ b, float* __restrict__ out)
{
    int t = blockIdx.x;
    int c = threadIdx.x;
    float x = in[(size_t)t * DIMM + c];
    float s = x, sq = x * x;
    #pragma unroll
    for (int o = 16; o; o >>= 1) {
        s  += __shfl_xor_sync(0xFFFFFFFFu, s,  o);
        sq += __shfl_xor_sync(0xFFFFFFFFu, sq, o);
    }
    __shared__ float sh1[8], sh2[8];
    int w = c >> 5, l = c & 31;
    if (l == 0) { sh1[w] = s; sh2[w] = sq; }
    __syncthreads();
    if (w == 0) {
        s = sh1[l & 7]; sq = sh2[l & 7];
        #pragma unroll
        for (int o = 4; o; o >>= 1) {
            s  += __shfl_xor_sync(0xFFFFFFFFu, s,  o);
            sq += __shfl_xor_sync(0xFFFFFFFFu, sq, o);
        }
        if (l == 0) { sh1[0] = s; sh2[0] = sq; }
    }
    __syncthreads();
    float mean = sh1[0] * (1.0f / DIMM);
    float var  = sh2[0] * (1.0f / DIMM) - mean * mean;
    float rstd = rsqrtf(var + 1e-5f);
    out[(size_t)t * DIMM + c] = (x - mean) * rstd * g[c] + b[c];
}

// ---------------------------------------------------------------------------
// GEMM body: C[128 x 64 tile] = A[8192 x K] @ W[K x Nc] + bias
//   f32x2 micro-kernel: 8 rows (4 pairs) x 4 cols per thread.
// ---------------------------------------------------------------------------
template<int K, bool DOGELU, bool RES>
__device__ __forceinline__ void gemm_body(
    const float* __restrict__ A, const float* __restrict__ W,
    const float* __restrict__ bias, float* __restrict__ C, int Nc,
    int m0, int n0, float (*AsT)[132], float (*Ws)[64])
{
    int tid = threadIdx.x;
    int tx = tid & 15, ty = tid >> 4;

    u64 acc[4][4];
    #pragma unroll
    for (int i = 0; i < 4; ++i)
        #pragma unroll
        for (int j = 0; j < 4; ++j) acc[i][j] = 0ULL;

    for (int kt = 0; kt < K / 16; ++kt) {
        int k0 = kt * 16;
        #pragma unroll
        for (int p = 0; p < 2; ++p) {                 // A tile 128x16 -> AsT
            int qi = tid + p * 256;
            int r = qi >> 2, c4 = qi & 3;
            float4 a = *(const float4*)(A + (size_t)(m0 + r) * K + k0 + c4 * 4);
            AsT[c4 * 4 + 0][r] = a.x; AsT[c4 * 4 + 1][r] = a.y;
            AsT[c4 * 4 + 2][r] = a.z; AsT[c4 * 4 + 3][r] = a.w;
        }
        {                                             // W tile 16x64
            int kk = tid >> 4, c4 = tid & 15;
            *(float4*)&Ws[kk][c4 * 4] =
                *(const float4*)(W + (size_t)(k0 + kk) * Nc + n0 + c4 * 4);
        }
        __syncthreads();
        #pragma unroll
        for (int kk = 0; kk < 16; ++kk) {
            float4 b4 = *(float4*)&Ws[kk][tx * 4];
            u64 bb[4] = { pack2(b4.x, b4.x), pack2(b4.y, b4.y),
                          pack2(b4.z, b4.z), pack2(b4.w, b4.w) };
            u64 ap[4];
            #pragma unroll
            for (int i = 0; i < 4; ++i)
                ap[i] = *(const u64*)&AsT[kk][ty * 8 + 2 * i];
            #pragma unroll
            for (int i = 0; i < 4; ++i)
                #pragma unroll
                for (int j = 0; j < 4; ++j)
                    acc[i][j] = fma2(ap[i], bb[j], acc[i][j]);
        }
        __syncthreads();
    }

    #pragma unroll
    for (int i = 0; i < 4; ++i) {
        int r0 = m0 + ty * 8 + 2 * i;
        float o0[4], o1[4];
        #pragma unroll
        for (int j = 0; j < 4; ++j) unpack2(acc[i][j], o0[j], o1[j]);
        int cc = n0 + tx * 4;
        float4 bv = *(const float4*)(bias + cc);
        float bvf[4] = {bv.x, bv.y, bv.z, bv.w};
        #pragma unroll
        for (int j = 0; j < 4; ++j) { o0[j] += bvf[j]; o1[j] += bvf[j]; }
        if (DOGELU) {
            #pragma unroll
            for (int j = 0; j < 4; ++j) {
                o0[j] = 0.5f * o0[j] * (1.0f + erff(o0[j] * 0.70710678118654752f));
                o1[j] = 0.5f * o1[j] * (1.0f + erff(o1[j] * 0.70710678118654752f));
            }
        }
        size_t i0 = (size_t)r0 * Nc + cc, i1 = i0 + Nc;
        if (RES) {
            float4 c0 = *(float4*)(C + i0);
            float4 c1 = *(float4*)(C + i1);
            o0[0] += c0.x; o0[1] += c0.y; o0[2] += c0.z; o0[3] += c0.w;
            o1[0] += c1.x; o1[1] += c1.y; o1[2] += c1.z; o1[3] += c1.w;
        }
        *(float4*)(C + i0) = make_float4(o0[0], o0[1], o0[2], o0[3]);
        *(float4*)(C + i1) = make_float4(o1[0], o1[1], o1[2], o1[3]);
    }
}

template<int K, bool DOGELU, bool RES>
__global__ void __launch_bounds__(256) gemm_kernel(
    const float* __restrict__ A, const float* __restrict__ W,
    const float* __restrict__ bias, float* __restrict__ C, int Nc)
{
    __shared__ __align__(16) float AsT[16][132];
    __shared__ __align__(16) float Ws [16][64];
    gemm_body<K, DOGELU, RES>(A, W, bias, C, Nc,
                              blockIdx.y * 128, blockIdx.x * 64, AsT, Ws);
}

// Fused QKV projection: grid (12, 64); blockIdx.x selects matrix + n-tile.
__global__ void __launch_bounds__(256) qkv_kernel(
    const float* __restrict__ A,
    const float* __restrict__ Wq, const float* __restrict__ bq, float* __restrict__ Cq,
    const float* __restrict__ Wk, const float* __restrict__ bk, float* __restrict__ Ck,
    const float* __restrict__ Wv, const float* __restrict__ bv, float* __restrict__ Cv)
{
    __shared__ __align__(16) float AsT[16][132];
    __shared__ __align__(16) float Ws [16][64];
    int which = blockIdx.x >> 2;
    int n0 = (blockIdx.x & 3) * 64;
    const float* W = (which == 0) ? Wq : (which == 1) ? Wk : Wv;
    const float* b = (which == 0) ? bq : (which == 1) ? bk : bv;
    float*       C = (which == 0) ? Cq : (which == 1) ? Ck : Cv;
    gemm_body<256, false, false>(A, W, b, C, 256, blockIdx.y * 128, n0, AsT, Ws);
}

// ---------------------------------------------------------------------------
// Flash attention: per block one (z, q-tile of 64 rows). Loops over 16 kv
// tiles of 64; computes S tile (+bias), running-max softmax, PV accumulate.
//   z = blockIdx.y: s = z>>5, b = (z>>3)&3, h = z&7
// ---------------------------------------------------------------------------
template<bool HASBIAS>
__global__ void __launch_bounds__(256) flash_kernel(
    const float* __restrict__ Q, const float* __restrict__ Km,
    const float* __restrict__ V,
    const float* __restrict__ biasS, const float* __restrict__ biasT,
    float* __restrict__ O, int kv_swap)
{
    __shared__ __align__(16) float QsT[32][68];   // [d][n]
    __shared__ __align__(16) float KsT[32][68];   // [d][m]
    __shared__ __align__(16) float Vs [64][36];   // [m][d]
    __shared__ __align__(16) float PsT[64][68];   // [m][n]
    __shared__ float m_state[64], l_state[64], alpha_sh[64];

    int tid = threadIdx.x;
    int nt = blockIdx.x, z = blockIdx.y;
    int s = z >> 5, b = (z >> 3) & 3, h = z & 7;
    int qb = s * 4096 + b * 1024 + nt * 64;
    int ks = kv_swap ? (1 - s) : s;
    int kvb = ks * 4096 + b * 1024;

    const float* bias = nullptr;
    if (HASBIAS)
        bias = ((s == 0) ? biasS : biasT)
             + ((size_t)(b * NHEAD + h) * NSEQ + (size_t)nt * 64) * NSEQ;

    // load Q tile (64 x 32, transposed)
    #pragma unroll
    for (int p = 0; p < 2; ++p) {
        int qi = tid + p * 256;
        int r = qi >> 3, c4 = qi & 7;
        float4 a = *(const float4*)(Q + (size_t)(qb + r) * DIMM + h * 32 + c4 * 4);
        QsT[c4 * 4 + 0][r] = a.x; QsT[c4 * 4 + 1][r] = a.y;
        QsT[c4 * 4 + 2][r] = a.z; QsT[c4 * 4 + 3][r] = a.w;
    }
    if (tid < 64) { m_state[tid] = -1e30f; l_state[tid] = 0.0f; }

    // persistent O accumulator: PV layout (tx2 = d in 0..31, ty2 = rowgroup)
    int tx2 = tid & 31, ty2 = tid >> 5;
    u64 accv[4] = {0ULL, 0ULL, 0ULL, 0ULL};

    // S layout
    int tx = tid & 15, ty = tid >> 4;
    int r0 = ty * 4;

    for (int jt = 0; jt < 16; ++jt) {
        // ---- load K (transposed) and V tiles ----
        #pragma unroll
        for (int p = 0; p < 2; ++p) {
            int qi = tid + p * 256;
            int r = qi >> 3, c4 = qi & 7;
            float4 kk = *(const float4*)(Km + (size_t)(kvb + jt * 64 + r) * DIMM + h * 32 + c4 * 4);
            KsT[c4 * 4 + 0][r] = kk.x; KsT[c4 * 4 + 1][r] = kk.y;
            KsT[c4 * 4 + 2][r] = kk.z; KsT[c4 * 4 + 3][r] = kk.w;
            float4 vv = *(const float4*)(V + (size_t)(kvb + jt * 64 + r) * DIMM + h * 32 + c4 * 4);
            *(float4*)&Vs[r][c4 * 4] = vv;
        }
        __syncthreads();

        // ---- S tile: 4 rows (2 pairs) x 4 cols per thread ----
        u64 sacc[2][4];
        #pragma unroll
        for (int i = 0; i < 2; ++i)
            #pragma unroll
            for (int j = 0; j < 4; ++j) sacc[i][j] = 0ULL;
        #pragma unroll
        for (int d = 0; d < 32; ++d) {
            float4 k4 = *(float4*)&KsT[d][tx * 4];
            u64 bb[4] = { pack2(k4.x, k4.x), pack2(k4.y, k4.y),
                          pack2(k4.z, k4.z), pack2(k4.w, k4.w) };
            u64 a0 = *(const u64*)&QsT[d][r0];
            u64 a1 = *(const u64*)&QsT[d][r0 + 2];
            #pragma unroll
            for (int j = 0; j < 4; ++j) {
                sacc[0][j] = fma2(a0, bb[j], sacc[0][j]);
                sacc[1][j] = fma2(a1, bb[j], sacc[1][j]);
            }
        }
        float s4[4][4];
        #pragma unroll
        for (int i2 = 0; i2 < 2; ++i2)
            #pragma unroll
            for (int j = 0; j < 4; ++j)
                unpack2(sacc[i2][j], s4[2 * i2][j], s4[2 * i2 + 1][j]);

        #pragma unroll
        for (int i = 0; i < 4; ++i) {
            if (HASBIAS) {
                float4 bv = *(const float4*)(bias + (size_t)(r0 + i) * NSEQ + jt * 64 + tx * 4);
                s4[i][0] = s4[i][0] * ATT_SCALE + bv.x;
                s4[i][1] = s4[i][1] * ATT_SCALE + bv.y;
                s4[i][2] = s4[i][2] * ATT_SCALE + bv.z;
                s4[i][3] = s4[i][3] * ATT_SCALE + bv.w;
            } else {
                s4[i][0] *= ATT_SCALE; s4[i][1] *= ATT_SCALE;
                s4[i][2] *= ATT_SCALE; s4[i][3] *= ATT_SCALE;
            }
        }

        // ---- per-row running softmax ----
        #pragma unroll
        for (int i = 0; i < 4; ++i) {
            float rmax = fmaxf(fmaxf(s4[i][0], s4[i][1]), fmaxf(s4[i][2], s4[i][3]));
            #pragma unroll
            for (int o = 8; o; o >>= 1)
                rmax = fmaxf(rmax, __shfl_xor_sync(0xFFFFFFFFu, rmax, o));
            float m_old = m_state[r0 + i];
            float m_new = fmaxf(m_old, rmax);
            float rsum = 0.0f;
            #pragma unroll
            for (int j = 0; j < 4; ++j) {
                s4[i][j] = __expf(s4[i][j] - m_new);
                rsum += s4[i][j];
            }
            #pragma unroll
            for (int o = 8; o; o >>= 1)
                rsum += __shfl_xor_sync(0xFFFFFFFFu, rsum, o);
            if (tx == 0) {
                float al = __expf(m_old - m_new);
                m_state[r0 + i]  = m_new;
                alpha_sh[r0 + i] = al;
                l_state[r0 + i]  = l_state[r0 + i] * al + rsum;
            }
            // write transposed P
            #pragma unroll
            for (int j = 0; j < 4; ++j)
                PsT[tx * 4 + j][r0 + i] = s4[i][j];
        }
        __syncthreads();

        // ---- PV accumulate: 8 rows (4 pairs) x 1 col (d = tx2) per thread ----
        #pragma unroll
        for (int i = 0; i < 4; ++i) {
            u64 al = pack2(alpha_sh[ty2 * 8 + 2 * i], alpha_sh[ty2 * 8 + 2 * i + 1]);
            accv[i] = mul2(accv[i], al);
        }
        #pragma unroll 4
        for (int mk = 0; mk < 64; ++mk) {
            float vvf = Vs[mk][tx2];
            u64 vv = pack2(vvf, vvf);
            #pragma unroll
            for (int i = 0; i < 4; ++i) {
                u64 pp = *(const u64*)&PsT[mk][ty2 * 8 + 2 * i];
                accv[i] = fma2(pp, vv, accv[i]);
            }
        }
        __syncthreads();
    }

    // ---- final normalize + store ----
    #pragma unroll
    for (int i = 0; i < 4; ++i) {
        int rr = ty2 * 8 + 2 * i;
        float inv0 = 1.0f / l_state[rr];
        float inv1 = 1.0f / l_state[rr + 1];
        float v0, v1;
        unpack2(accv[i], v0, v1);
        O[(size_t)(qb + rr)     * DIMM + h * 32 + tx2] = v0 * inv0;
        O[(size_t)(qb + rr + 1) * DIMM + h * 32 + tx2] = v1 * inv1;
    }
}

// ---------------------------------------------------------------------------
// Host orchestration
// ---------------------------------------------------------------------------
extern "C" void kernel_launch(void* const* d_in, const int* in_sizes, int n_in,
                              void* d_out, int out_size)
{
    (void)in_sizes; (void)n_in; (void)out_size;

    const float* src   = (const float*)d_in[0];
    const float* tgt   = (const float*)d_in[1];
    const float* biasS = (const float*)d_in[2];
    const float* biasT = (const float*)d_in[3];
    // 4..11: sa q_w,q_b,k_w,k_b,v_w,v_b,o_w,o_b ; 12..19: ca same
    // 20..25: ln_sa_g, ln_sa_b, ln_ca_g, ln_ca_b, ln_ff_g, ln_ff_b
    // 26..29: ffn_w1, ffn_b1, ffn_w2, ffn_b2
    #define IN(i) ((const float*)d_in[(i)])

    float *xn, *q, *k, *v, *att, *hbuf;
    cudaGetSymbolAddress((void**)&xn,   g_xn);
    cudaGetSymbolAddress((void**)&q,    g_q);
    cudaGetSymbolAddress((void**)&k,    g_k);
    cudaGetSymbolAddress((void**)&v,    g_v);
    cudaGetSymbolAddress((void**)&att,  g_att);
    cudaGetSymbolAddress((void**)&hbuf, g_h);

    float* cur = (float*)d_out;     // running residual; stream 0 then stream 1
    size_t half = (size_t)4096 * DIMM * sizeof(float);
    cudaMemcpyAsync(cur, src, half, cudaMemcpyDeviceToDevice);
    cudaMemcpyAsync(cur + (size_t)4096 * DIMM, tgt, half, cudaMemcpyDeviceToDevice);

    dim3 gProj(4, 64);      // Nc=256 GEMMs over 8192 tokens
    dim3 gQkv(12, 64);
    dim3 gFfn1(16, 64);     // Nc=1024
    dim3 gFlash(16, 64);

    // ---- stage 1: geometric self-attention (pre-norm residual) ----
    ln_kernel<<<TOKS, 256>>>(cur, IN(20), IN(21), xn);
    qkv_kernel<<<gQkv, 256>>>(xn, IN(4), IN(5), q, IN(6), IN(7), k, IN(8), IN(9), v);
    flash_kernel<true><<<gFlash, 256>>>(q, k, v, biasS, biasT, att, 0);
    gemm_kernel<256, false, true><<<gProj, 256>>>(att, IN(10), IN(11), cur, 256);

    // ---- stage 2: cross-attention (kv from the other stream) ----
    ln_kernel<<<TOKS, 256>>>(cur, IN(22), IN(23), xn);
    qkv_kernel<<<gQkv, 256>>>(xn, IN(12), IN(13), q, IN(14), IN(15), k, IN(16), IN(17), v);
    flash_kernel<false><<<gFlash, 256>>>(q, k, v, nullptr, nullptr, att, 1);
    gemm_kernel<256, false, true><<<gProj, 256>>>(att, IN(18), IN(19), cur, 256);

    // ---- stage 3: FFN ----
    ln_kernel<<<TOKS, 256>>>(cur, IN(24), IN(25), xn);
    gemm_kernel<256,  true,  false><<<gFfn1, 256>>>(xn,   IN(26), IN(27), hbuf, 1024);
    gemm_kernel<1024, false, true ><<<gProj, 256>>>(hbuf, IN(28), IN(29), cur,  256);

    #undef IN
}

// round 10
// speedup vs baseline: 1.5306x; 1.5306x over previous
#include <cuda_runtime.h>
#include <math.h>
#include <stddef.h>
#include <stdint.h>

// ---------------------------------------------------------------------------
// GeometricCrossAttentionBlock — tf32 tensor-core GEMMs + fp32 attention
//   streams: 0 = src (tokens 0..4095), 1 = tgt (tokens 4096..8191)
//   d_out doubles as the running residual buffer "cur" [8192][256]
// ---------------------------------------------------------------------------

#define TOKS   8192
#define DIMM   256
#define NSEQ   1024
#define NHEAD  8
#define HDIM   32
#define FFND   1024
#define ATT_SCALE 0.17677669529663687f   /* 32^-0.5 */

// -------------------- device scratch (allocation-free rule) ----------------
__device__ float g_xn [TOKS * DIMM];            //  8 MB   LN output
__device__ float g_q  [TOKS * DIMM];            //  8 MB
__device__ float g_k  [TOKS * DIMM];            //  8 MB
__device__ float g_v  [TOKS * DIMM];            //  8 MB
__device__ float g_att[TOKS * DIMM];            //  8 MB   attention out (pre O-proj)
__device__ float g_h  [TOKS * FFND];            // 32 MB   FFN hidden
__device__ float g_scores[67108864];            // 256 MB  [2][4][8][1024][1024]

// -------------------- tf32 helpers -----------------------------------------
__device__ __forceinline__ uint32_t tf32_of(float x) {
    uint32_t r; asm("cvt.rna.tf32.f32 %0, %1;" : "=r"(r) : "f"(x)); return r;
}
__device__ __forceinline__ void mma_tf32(
    float& d0, float& d1, float& d2, float& d3,
    uint32_t a0, uint32_t a1, uint32_t a2, uint32_t a3,
    uint32_t b0, uint32_t b1)
{
    asm volatile(
        "mma.sync.aligned.m16n8k8.row.col.f32.tf32.tf32.f32 "
        "{%0,%1,%2,%3}, {%4,%5,%6,%7}, {%8,%9}, {%0,%1,%2,%3};"
        : "+f"(d0), "+f"(d1), "+f"(d2), "+f"(d3)
        : "r"(a0), "r"(a1), "r"(a2), "r"(a3), "r"(b0), "r"(b1));
}

// ---------------------------------------------------------------------------
// LayerNorm over last dim (256). One block (256 thr) per row.
// ---------------------------------------------------------------------------
__global__ void __launch_bounds__(256) ln_kernel(
    const float* __restrict__ in, const float* __restrict__ g,
    const float* __restrict__ b, float* __restrict__ out)
{
    int t = blockIdx.x;
    int c = threadIdx.x;
    float x = in[(size_t)t * DIMM + c];
    float s = x, sq = x * x;
    #pragma unroll
    for (int o = 16; o; o >>= 1) {
        s  += __shfl_xor_sync(0xFFFFFFFFu, s,  o);
        sq += __shfl_xor_sync(0xFFFFFFFFu, sq, o);
    }
    __shared__ float sh1[8], sh2[8];
    int w = c >> 5, l = c & 31;
    if (l == 0) { sh1[w] = s; sh2[w] = sq; }
    __syncthreads();
    if (w == 0) {
        s = sh1[l & 7]; sq = sh2[l & 7];
        #pragma unroll
        for (int o = 4; o; o >>= 1) {
            s  += __shfl_xor_sync(0xFFFFFFFFu, s,  o);
            sq += __shfl_xor_sync(0xFFFFFFFFu, sq, o);
        }
        if (l == 0) { sh1[0] = s; sh2[0] = sq; }
    }
    __syncthreads();
    float mean = sh1[0] * (1.0f / DIMM);
    float var  = sh2[0] * (1.0f / DIMM) - mean * mean;
    float rstd = rsqrtf(var + 1e-5f);
    out[(size_t)t * DIMM + c] = (x - mean) * rstd * g[c] + b[c];
}

// ---------------------------------------------------------------------------
// tf32 tensor-core GEMM: C[8192 x Nc] = A[8192 x K] @ W[K x Nc] + bias
//   128x64 block tile, 8 warps as 4(m) x 2(n), warp tile 32x32.
//   mma.m16n8k8: per warp 2 m-tiles x 4 n-tiles per k8 step, K-chunk = 16.
//   optional exact GELU epilogue, optional residual accumulate (C += ...)
// ---------------------------------------------------------------------------
template<int K, bool DOGELU, bool RES>
__global__ void __launch_bounds__(256) gemm_kernel(
    const float* __restrict__ A, const float* __restrict__ W,
    const float* __restrict__ bias, float* __restrict__ C, int Nc)
{
    __shared__ uint32_t As[128][20];   // [m][k], pad 16->20 (conflict-free frags)
    __shared__ uint32_t Ws[16][72];    // [k][n], pad 64->72 (conflict-free frags)

    int tid  = threadIdx.x;
    int lane = tid & 31, warp = tid >> 5;
    int wm = warp >> 1, wn = warp & 1;       // 4 x 2 warp grid
    int g = lane >> 2, t = lane & 3;         // mma quad coords
    int m0 = blockIdx.y * 128;
    int n0 = blockIdx.x * 64;

    float acc[2][4][4];
    #pragma unroll
    for (int mi = 0; mi < 2; ++mi)
        #pragma unroll
        for (int ni = 0; ni < 4; ++ni)
            #pragma unroll
            for (int r = 0; r < 4; ++r) acc[mi][ni][r] = 0.0f;

    for (int kt = 0; kt < K / 16; ++kt) {
        int k0 = kt * 16;
        // ---- stage A tile 128x16 (tf32) ----
        #pragma unroll
        for (int p = 0; p < 2; ++p) {
            int qi = tid + p * 256;
            int r = qi >> 2, c4 = qi & 3;
            float4 a = *(const float4*)(A + (size_t)(m0 + r) * K + k0 + c4 * 4);
            As[r][c4 * 4 + 0] = tf32_of(a.x);
            As[r][c4 * 4 + 1] = tf32_of(a.y);
            As[r][c4 * 4 + 2] = tf32_of(a.z);
            As[r][c4 * 4 + 3] = tf32_of(a.w);
        }
        // ---- stage W tile 16x64 (tf32) ----
        {
            int kk = tid >> 4, c4 = tid & 15;
            float4 w4 = *(const float4*)(W + (size_t)(k0 + kk) * Nc + n0 + c4 * 4);
            Ws[kk][c4 * 4 + 0] = tf32_of(w4.x);
            Ws[kk][c4 * 4 + 1] = tf32_of(w4.y);
            Ws[kk][c4 * 4 + 2] = tf32_of(w4.z);
            Ws[kk][c4 * 4 + 3] = tf32_of(w4.w);
        }
        __syncthreads();

        #pragma unroll
        for (int ks = 0; ks < 2; ++ks) {
            int ko = ks * 8;
            // A fragments for the 2 m-tiles of this warp
            uint32_t af[2][4];
            #pragma unroll
            for (int mi = 0; mi < 2; ++mi) {
                int rb = wm * 32 + mi * 16 + g;
                af[mi][0] = As[rb    ][ko + t];
                af[mi][1] = As[rb + 8][ko + t];
                af[mi][2] = As[rb    ][ko + t + 4];
                af[mi][3] = As[rb + 8][ko + t + 4];
            }
            #pragma unroll
            for (int ni = 0; ni < 4; ++ni) {
                int cb = wn * 32 + ni * 8 + g;
                uint32_t b0 = Ws[ko + t    ][cb];
                uint32_t b1 = Ws[ko + t + 4][cb];
                #pragma unroll
                for (int mi = 0; mi < 2; ++mi)
                    mma_tf32(acc[mi][ni][0], acc[mi][ni][1],
                             acc[mi][ni][2], acc[mi][ni][3],
                             af[mi][0], af[mi][1], af[mi][2], af[mi][3],
                             b0, b1);
            }
        }
        __syncthreads();
    }

    // ---- epilogue: bias (+GELU) (+residual), float2 stores ----
    #pragma unroll
    for (int mi = 0; mi < 2; ++mi) {
        int rlo = m0 + wm * 32 + mi * 16 + g;
        int rhi = rlo + 8;
        #pragma unroll
        for (int ni = 0; ni < 4; ++ni) {
            int col = n0 + wn * 32 + ni * 8 + t * 2;
            float2 bv = *(const float2*)(bias + col);
            float v0 = acc[mi][ni][0] + bv.x;
            float v1 = acc[mi][ni][1] + bv.y;
            float v2 = acc[mi][ni][2] + bv.x;
            float v3 = acc[mi][ni][3] + bv.y;
            if (DOGELU) {
                v0 = 0.5f * v0 * (1.0f + erff(v0 * 0.70710678118654752f));
                v1 = 0.5f * v1 * (1.0f + erff(v1 * 0.70710678118654752f));
                v2 = 0.5f * v2 * (1.0f + erff(v2 * 0.70710678118654752f));
                v3 = 0.5f * v3 * (1.0f + erff(v3 * 0.70710678118654752f));
            }
            size_t ilo = (size_t)rlo * Nc + col;
            size_t ihi = (size_t)rhi * Nc + col;
            if (RES) {
                float2 c0 = *(float2*)(C + ilo);
                float2 c1 = *(float2*)(C + ihi);
                v0 += c0.x; v1 += c0.y; v2 += c1.x; v3 += c1.y;
            }
            *(float2*)(C + ilo) = make_float2(v0, v1);
            *(float2*)(C + ihi) = make_float2(v2, v3);
        }
    }
}

// ---------------------------------------------------------------------------
// Scores: S[z, n, m] = SCALE * q[n,:] . k[m,:] (+ geo bias), z = (s*4+b)*8+h
//   64x64 output tile per block, full K=32 head dim in smem.  (proven R6)
// ---------------------------------------------------------------------------
__global__ void __launch_bounds__(256) scores_kernel(
    const float* __restrict__ Q, const float* __restrict__ Km,
    const float* __restrict__ biasS, const float* __restrict__ biasT,
    float* __restrict__ S, int kv_swap)
{
    __shared__ __align__(16) float QsT[32][68];   // [d][n]
    __shared__ __align__(16) float KsT[32][68];   // [d][m]
    int tid = threadIdx.x;
    int mt = blockIdx.x, nt = blockIdx.y, z = blockIdx.z;
    int s = z >> 5, bh = z & 31, b = bh >> 3, h = bh & 7;
    int qb = s * 4096 + b * 1024 + nt * 64;
    int ks = kv_swap ? (1 - s) : s;
    int kb = ks * 4096 + b * 1024 + mt * 64;

    #pragma unroll
    for (int p = 0; p < 2; ++p) {
        int qi = tid + p * 256;
        int r = qi >> 3, c4 = qi & 7;
        float4 a = *(const float4*)(Q  + (size_t)(qb + r) * DIMM + h * 32 + c4 * 4);
        QsT[c4 * 4 + 0][r] = a.x; QsT[c4 * 4 + 1][r] = a.y;
        QsT[c4 * 4 + 2][r] = a.z; QsT[c4 * 4 + 3][r] = a.w;
        float4 kk = *(const float4*)(Km + (size_t)(kb + r) * DIMM + h * 32 + c4 * 4);
        KsT[c4 * 4 + 0][r] = kk.x; KsT[c4 * 4 + 1][r] = kk.y;
        KsT[c4 * 4 + 2][r] = kk.z; KsT[c4 * 4 + 3][r] = kk.w;
    }
    __syncthreads();

    int tx = tid & 15, ty = tid >> 4;
    float acc[4][4];
    #pragma unroll
    for (int i = 0; i < 4; ++i)
        #pragma unroll
        for (int j = 0; j < 4; ++j) acc[i][j] = 0.0f;

    #pragma unroll
    for (int d = 0; d < 32; ++d) {
        float4 a = *(float4*)&QsT[d][ty * 4];
        float4 c = *(float4*)&KsT[d][tx * 4];
        float av[4] = {a.x, a.y, a.z, a.w};
        float cv[4] = {c.x, c.y, c.z, c.w};
        #pragma unroll
        for (int i = 0; i < 4; ++i)
            #pragma unroll
            for (int j = 0; j < 4; ++j)
                acc[i][j] = fmaf(av[i], cv[j], acc[i][j]);
    }

    const float* bias = (biasS == nullptr) ? nullptr : ((s == 0) ? biasS : biasT);
    #pragma unroll
    for (int i = 0; i < 4; ++i) {
        int n = nt * 64 + ty * 4 + i;
        #pragma unroll
        for (int j = 0; j < 4; ++j) {
            int m = mt * 64 + tx * 4 + j;
            float val = acc[i][j] * ATT_SCALE;
            if (bias)
                val += bias[((size_t)(b * NHEAD + h) * NSEQ + n) * NSEQ + m];
            S[((size_t)z * NSEQ + n) * NSEQ + m] = val;
        }
    }
}

// ---------------------------------------------------------------------------
// Softmax over last dim (1024), in place. One warp per row, 8 warps/block.
// ---------------------------------------------------------------------------
__global__ void __launch_bounds__(256) softmax_kernel(float* __restrict__ S)
{
    int warp = threadIdx.x >> 5, lane = threadIdx.x & 31;
    size_t row = (size_t)blockIdx.x * 8 + warp;
    float* p = S + row * NSEQ;

    float4 v[8];
    #pragma unroll
    for (int u = 0; u < 8; ++u) v[u] = *(float4*)(p + (lane + u * 32) * 4);

    float mx = -1e30f;
    #pragma unroll
    for (int u = 0; u < 8; ++u) {
        mx = fmaxf(mx, fmaxf(fmaxf(v[u].x, v[u].y), fmaxf(v[u].z, v[u].w)));
    }
    #pragma unroll
    for (int o = 16; o; o >>= 1) mx = fmaxf(mx, __shfl_xor_sync(0xFFFFFFFFu, mx, o));

    float sum = 0.0f;
    #pragma unroll
    for (int u = 0; u < 8; ++u) {
        v[u].x = __expf(v[u].x - mx); v[u].y = __expf(v[u].y - mx);
        v[u].z = __expf(v[u].z - mx); v[u].w = __expf(v[u].w - mx);
        sum += v[u].x + v[u].y + v[u].z + v[u].w;
    }
    #pragma unroll
    for (int o = 16; o; o >>= 1) sum += __shfl_xor_sync(0xFFFFFFFFu, sum, o);

    float r = 1.0f / sum;
    #pragma unroll
    for (int u = 0; u < 8; ++u) {
        v[u].x *= r; v[u].y *= r; v[u].z *= r; v[u].w *= r;
        *(float4*)(p + (lane + u * 32) * 4) = v[u];
    }
}

// ---------------------------------------------------------------------------
// PV: out[n, h*32+d] = sum_m P[z,n,m] * v[m, h*32+d]   (proven R6)
// ---------------------------------------------------------------------------
__global__ void __launch_bounds__(256) pv_kernel(
    const float* __restrict__ S, const float* __restrict__ V,
    float* __restrict__ O, int kv_swap)
{
    __shared__ __align__(16) float PsT[32][68];   // [m][n]
    __shared__ __align__(16) float Vs [32][32];   // [m][d]
    int tid = threadIdx.x;
    int nt = blockIdx.x, z = blockIdx.y;
    int s = z >> 5, bh = z & 31, b = bh >> 3, h = bh & 7;
    int qb  = s * 4096 + b * 1024;
    int ks  = kv_swap ? (1 - s) : s;
    int kvb = ks * 4096 + b * 1024;
    int tx = tid & 31, ty = tid >> 5;

    float acc[8];
    #pragma unroll
    for (int i = 0; i < 8; ++i) acc[i] = 0.0f;

    const float* Srow = S + ((size_t)z * NSEQ + nt * 64) * NSEQ;

    for (int mt = 0; mt < 32; ++mt) {
        #pragma unroll
        for (int p = 0; p < 2; ++p) {
            int qi = tid + p * 256;
            int r = qi >> 3, c4 = qi & 7;
            float4 a = *(const float4*)(Srow + (size_t)r * NSEQ + mt * 32 + c4 * 4);
            PsT[c4 * 4 + 0][r] = a.x; PsT[c4 * 4 + 1][r] = a.y;
            PsT[c4 * 4 + 2][r] = a.z; PsT[c4 * 4 + 3][r] = a.w;
        }
        {
            int r = tid >> 3, c4 = tid & 7;
            *(float4*)&Vs[r][c4 * 4] =
                *(const float4*)(V + (size_t)(kvb + mt * 32 + r) * DIMM + h * 32 + c4 * 4);
        }
        __syncthreads();
        #pragma unroll
        for (int mk = 0; mk < 32; ++mk) {
            float vv = Vs[mk][tx];
            float4 p0 = *(float4*)&PsT[mk][ty * 8];
            float4 p1 = *(float4*)&PsT[mk][ty * 8 + 4];
            acc[0] = fmaf(p0.x, vv, acc[0]); acc[1] = fmaf(p0.y, vv, acc[1]);
            acc[2] = fmaf(p0.z, vv, acc[2]); acc[3] = fmaf(p0.w, vv, acc[3]);
            acc[4] = fmaf(p1.x, vv, acc[4]); acc[5] = fmaf(p1.y, vv, acc[5]);
            acc[6] = fmaf(p1.z, vv, acc[6]); acc[7] = fmaf(p1.w, vv, acc[7]);
        }
        __syncthreads();
    }
    #pragma unroll
    for (int i = 0; i < 8; ++i)
        O[(size_t)(qb + nt * 64 + ty * 8 + i) * DIMM + h * 32 + tx] = acc[i];
}

// ---------------------------------------------------------------------------
// Host orchestration
// ---------------------------------------------------------------------------
extern "C" void kernel_launch(void* const* d_in, const int* in_sizes, int n_in,
                              void* d_out, int out_size)
{
    (void)in_sizes; (void)n_in; (void)out_size;

    const float* src   = (const float*)d_in[0];
    const float* tgt   = (const float*)d_in[1];
    const float* biasS = (const float*)d_in[2];
    const float* biasT = (const float*)d_in[3];
    // 4..11: sa q_w,q_b,k_w,k_b,v_w,v_b,o_w,o_b ; 12..19: ca same
    // 20..25: ln_sa_g, ln_sa_b, ln_ca_g, ln_ca_b, ln_ff_g, ln_ff_b
    // 26..29: ffn_w1, ffn_b1, ffn_w2, ffn_b2
    #define IN(i) ((const float*)d_in[(i)])

    float *xn, *q, *k, *v, *att, *hbuf, *sc;
    cudaGetSymbolAddress((void**)&xn,   g_xn);
    cudaGetSymbolAddress((void**)&q,    g_q);
    cudaGetSymbolAddress((void**)&k,    g_k);
    cudaGetSymbolAddress((void**)&v,    g_v);
    cudaGetSymbolAddress((void**)&att,  g_att);
    cudaGetSymbolAddress((void**)&hbuf, g_h);
    cudaGetSymbolAddress((void**)&sc,   g_scores);

    float* cur = (float*)d_out;     // running residual; stream 0 then stream 1
    size_t half = (size_t)4096 * DIMM * sizeof(float);
    cudaMemcpyAsync(cur, src, half, cudaMemcpyDeviceToDevice);
    cudaMemcpyAsync(cur + (size_t)4096 * DIMM, tgt, half, cudaMemcpyDeviceToDevice);

    dim3 gProj(4, 64);      // Nc=256 GEMMs over 8192 tokens
    dim3 gFfn1(16, 64);     // Nc=1024
    dim3 gScore(16, 16, 64);
    dim3 gPV(16, 64);

    // ---- stage 1: geometric self-attention (pre-norm residual) ----
    ln_kernel<<<TOKS, 256>>>(cur, IN(20), IN(21), xn);
    gemm_kernel<256, false, false><<<gProj, 256>>>(xn, IN(4),  IN(5),  q, 256);
    gemm_kernel<256, false, false><<<gProj, 256>>>(xn, IN(6),  IN(7),  k, 256);
    gemm_kernel<256, false, false><<<gProj, 256>>>(xn, IN(8),  IN(9),  v, 256);
    scores_kernel<<<gScore, 256>>>(q, k, biasS, biasT, sc, 0);
    softmax_kernel<<<TOKS, 256>>>(sc);
    pv_kernel<<<gPV, 256>>>(sc, v, att, 0);
    gemm_kernel<256, false, true><<<gProj, 256>>>(att, IN(10), IN(11), cur, 256);

    // ---- stage 2: cross-attention (kv from the other stream) ----
    ln_kernel<<<TOKS, 256>>>(cur, IN(22), IN(23), xn);
    gemm_kernel<256, false, false><<<gProj, 256>>>(xn, IN(12), IN(13), q, 256);
    gemm_kernel<256, false, false><<<gProj, 256>>>(xn, IN(14), IN(15), k, 256);
    gemm_kernel<256, false, false><<<gProj, 256>>>(xn, IN(16), IN(17), v, 256);
    scores_kernel<<<gScore, 256>>>(q, k, nullptr, nullptr, sc, 1);
    softmax_kernel<<<TOKS, 256>>>(sc);
    pv_kernel<<<gPV, 256>>>(sc, v, att, 1);
    gemm_kernel<256, false, true><<<gProj, 256>>>(att, IN(18), IN(19), cur, 256);

    // ---- stage 3: FFN ----
    ln_kernel<<<TOKS, 256>>>(cur, IN(24), IN(25), xn);
    gemm_kernel<256,  true,  false><<<gFfn1, 256>>>(xn,   IN(26), IN(27), hbuf, 1024);
    gemm_kernel<1024, false, true ><<<gProj, 256>>>(hbuf, IN(28), IN(29), cur,  256);

    #undef IN
}

// round 11
// speedup vs baseline: 2.8587x; 1.8677x over previous
#include <cuda_runtime.h>
#include <math.h>
#include <stddef.h>
#include <stdint.h>

// ---------------------------------------------------------------------------
// GeometricCrossAttentionBlock — tf32 tensor-core GEMMs + tf32 flash attention
//   streams: 0 = src (tokens 0..4095), 1 = tgt (tokens 4096..8191)
//   d_out doubles as the running residual buffer "cur" [8192][256]
// ---------------------------------------------------------------------------

#define TOKS   8192
#define DIMM   256
#define NSEQ   1024
#define NHEAD  8
#define HDIM   32
#define FFND   1024
#define ATT_SCALE 0.17677669529663687f   /* 32^-0.5 */

// -------------------- device scratch (allocation-free rule) ----------------
__device__ float g_xn [TOKS * DIMM];            //  8 MB   LN output
__device__ float g_q  [TOKS * DIMM];            //  8 MB
__device__ float g_k  [TOKS * DIMM];            //  8 MB
__device__ float g_v  [TOKS * DIMM];            //  8 MB
__device__ float g_att[TOKS * DIMM];            //  8 MB   attention out (pre O-proj)
__device__ float g_h  [TOKS * FFND];            // 32 MB   FFN hidden

// -------------------- tf32 helpers -----------------------------------------
__device__ __forceinline__ uint32_t tf32_of(float x) {
    uint32_t r; asm("cvt.rna.tf32.f32 %0, %1;" : "=r"(r) : "f"(x)); return r;
}
__device__ __forceinline__ void mma_tf32(
    float& d0, float& d1, float& d2, float& d3,
    uint32_t a0, uint32_t a1, uint32_t a2, uint32_t a3,
    uint32_t b0, uint32_t b1)
{
    asm volatile(
        "mma.sync.aligned.m16n8k8.row.col.f32.tf32.tf32.f32 "
        "{%0,%1,%2,%3}, {%4,%5,%6,%7}, {%8,%9}, {%0,%1,%2,%3};"
        : "+f"(d0), "+f"(d1), "+f"(d2), "+f"(d3)
        : "r"(a0), "r"(a1), "r"(a2), "r"(a3), "r"(b0), "r"(b1));
}

// ---------------------------------------------------------------------------
// LayerNorm over last dim (256). One block (256 thr) per row.
// ---------------------------------------------------------------------------
__global__ void __launch_bounds__(256) ln_kernel(
    const float* __restrict__ in, const float* __restrict__ g,
    const float* __restrict__ b, float* __restrict__ out)
{
    int t = blockIdx.x;
    int c = threadIdx.x;
    float x = in[(size_t)t * DIMM + c];
    float s = x, sq = x * x;
    #pragma unroll
    for (int o = 16; o; o >>= 1) {
        s  += __shfl_xor_sync(0xFFFFFFFFu, s,  o);
        sq += __shfl_xor_sync(0xFFFFFFFFu, sq, o);
    }
    __shared__ float sh1[8], sh2[8];
    int w = c >> 5, l = c & 31;
    if (l == 0) { sh1[w] = s; sh2[w] = sq; }
    __syncthreads();
    if (w == 0) {
        s = sh1[l & 7]; sq = sh2[l & 7];
        #pragma unroll
        for (int o = 4; o; o >>= 1) {
            s  += __shfl_xor_sync(0xFFFFFFFFu, s,  o);
            sq += __shfl_xor_sync(0xFFFFFFFFu, sq, o);
        }
        if (l == 0) { sh1[0] = s; sh2[0] = sq; }
    }
    __syncthreads();
    float mean = sh1[0] * (1.0f / DIMM);
    float var  = sh2[0] * (1.0f / DIMM) - mean * mean;
    float rstd = rsqrtf(var + 1e-5f);
    out[(size_t)t * DIMM + c] = (x - mean) * rstd * g[c] + b[c];
}

// ---------------------------------------------------------------------------
// tf32 tensor-core GEMM (proven R10): C = A[8192 x K] @ W[K x Nc] + bias
// ---------------------------------------------------------------------------
template<int K, bool DOGELU, bool RES>
__global__ void __launch_bounds__(256) gemm_kernel(
    const float* __restrict__ A, const float* __restrict__ W,
    const float* __restrict__ bias, float* __restrict__ C, int Nc)
{
    __shared__ uint32_t As[128][20];
    __shared__ uint32_t Ws[16][72];

    int tid  = threadIdx.x;
    int lane = tid & 31, warp = tid >> 5;
    int wm = warp >> 1, wn = warp & 1;
    int g = lane >> 2, t = lane & 3;
    int m0 = blockIdx.y * 128;
    int n0 = blockIdx.x * 64;

    float acc[2][4][4];
    #pragma unroll
    for (int mi = 0; mi < 2; ++mi)
        #pragma unroll
        for (int ni = 0; ni < 4; ++ni)
            #pragma unroll
            for (int r = 0; r < 4; ++r) acc[mi][ni][r] = 0.0f;

    for (int kt = 0; kt < K / 16; ++kt) {
        int k0 = kt * 16;
        #pragma unroll
        for (int p = 0; p < 2; ++p) {
            int qi = tid + p * 256;
            int r = qi >> 2, c4 = qi & 3;
            float4 a = *(const float4*)(A + (size_t)(m0 + r) * K + k0 + c4 * 4);
            As[r][c4 * 4 + 0] = tf32_of(a.x);
            As[r][c4 * 4 + 1] = tf32_of(a.y);
            As[r][c4 * 4 + 2] = tf32_of(a.z);
            As[r][c4 * 4 + 3] = tf32_of(a.w);
        }
        {
            int kk = tid >> 4, c4 = tid & 15;
            float4 w4 = *(const float4*)(W + (size_t)(k0 + kk) * Nc + n0 + c4 * 4);
            Ws[kk][c4 * 4 + 0] = tf32_of(w4.x);
            Ws[kk][c4 * 4 + 1] = tf32_of(w4.y);
            Ws[kk][c4 * 4 + 2] = tf32_of(w4.z);
            Ws[kk][c4 * 4 + 3] = tf32_of(w4.w);
        }
        __syncthreads();

        #pragma unroll
        for (int ks = 0; ks < 2; ++ks) {
            int ko = ks * 8;
            uint32_t af[2][4];
            #pragma unroll
            for (int mi = 0; mi < 2; ++mi) {
                int rb = wm * 32 + mi * 16 + g;
                af[mi][0] = As[rb    ][ko + t];
                af[mi][1] = As[rb + 8][ko + t];
                af[mi][2] = As[rb    ][ko + t + 4];
                af[mi][3] = As[rb + 8][ko + t + 4];
            }
            #pragma unroll
            for (int ni = 0; ni < 4; ++ni) {
                int cb = wn * 32 + ni * 8 + g;
                uint32_t b0 = Ws[ko + t    ][cb];
                uint32_t b1 = Ws[ko + t + 4][cb];
                #pragma unroll
                for (int mi = 0; mi < 2; ++mi)
                    mma_tf32(acc[mi][ni][0], acc[mi][ni][1],
                             acc[mi][ni][2], acc[mi][ni][3],
                             af[mi][0], af[mi][1], af[mi][2], af[mi][3],
                             b0, b1);
            }
        }
        __syncthreads();
    }

    #pragma unroll
    for (int mi = 0; mi < 2; ++mi) {
        int rlo = m0 + wm * 32 + mi * 16 + g;
        int rhi = rlo + 8;
        #pragma unroll
        for (int ni = 0; ni < 4; ++ni) {
            int col = n0 + wn * 32 + ni * 8 + t * 2;
            float2 bv = *(const float2*)(bias + col);
            float v0 = acc[mi][ni][0] + bv.x;
            float v1 = acc[mi][ni][1] + bv.y;
            float v2 = acc[mi][ni][2] + bv.x;
            float v3 = acc[mi][ni][3] + bv.y;
            if (DOGELU) {
                v0 = 0.5f * v0 * (1.0f + erff(v0 * 0.70710678118654752f));
                v1 = 0.5f * v1 * (1.0f + erff(v1 * 0.70710678118654752f));
                v2 = 0.5f * v2 * (1.0f + erff(v2 * 0.70710678118654752f));
                v3 = 0.5f * v3 * (1.0f + erff(v3 * 0.70710678118654752f));
            }
            size_t ilo = (size_t)rlo * Nc + col;
            size_t ihi = (size_t)rhi * Nc + col;
            if (RES) {
                float2 c0 = *(float2*)(C + ilo);
                float2 c1 = *(float2*)(C + ihi);
                v0 += c0.x; v1 += c0.y; v2 += c1.x; v3 += c1.y;
            }
            *(float2*)(C + ilo) = make_float2(v0, v1);
            *(float2*)(C + ihi) = make_float2(v2, v3);
        }
    }
}

// ---------------------------------------------------------------------------
// Flash attention (tf32 mma): one block = (z, 128-row q-tile).
//   z = blockIdx.y: s = z>>5, b = (z>>3)&3, h = z&7
//   8 warps x 16 q-rows; kv-tiles of 32; softmax state in registers.
// ---------------------------------------------------------------------------
template<bool HASBIAS>
__global__ void __launch_bounds__(256) flash_kernel(
    const float* __restrict__ Qm, const float* __restrict__ Km,
    const float* __restrict__ Vm,
    const float* __restrict__ biasS, const float* __restrict__ biasT,
    float* __restrict__ O, int kv_swap)
{
    __shared__ uint32_t Qs [128][36];   // [row][d]    tf32
    __shared__ uint32_t KsT[32][36];    // [d][m]      tf32
    __shared__ uint32_t Vs [32][36];    // [m][d]      tf32
    __shared__ uint32_t Ps [128][36];   // [row][m]    tf32

    int tid = threadIdx.x, lane = tid & 31, warp = tid >> 5;
    int g = lane >> 2, t = lane & 3;
    int z = blockIdx.y;
    int s = z >> 5, b = (z >> 3) & 3, h = z & 7;
    int qb = s * 4096 + b * 1024 + blockIdx.x * 128;
    int ksel = kv_swap ? (1 - s) : s;
    int kvb = ksel * 4096 + b * 1024;
    int rb = warp * 16;

    // ---- stage Q tile (128 x 32) ----
    #pragma unroll
    for (int p = 0; p < 4; ++p) {
        int idx = tid + p * 256;
        int r = idx >> 3, c4 = idx & 7;
        float4 a = *(const float4*)(Qm + (size_t)(qb + r) * DIMM + h * 32 + c4 * 4);
        Qs[r][c4 * 4 + 0] = tf32_of(a.x);
        Qs[r][c4 * 4 + 1] = tf32_of(a.y);
        Qs[r][c4 * 4 + 2] = tf32_of(a.z);
        Qs[r][c4 * 4 + 3] = tf32_of(a.w);
    }

    const float* biasR0 = nullptr;
    const float* biasR1 = nullptr;
    if (HASBIAS) {
        const float* bb = ((s == 0) ? biasS : biasT)
                        + (size_t)(b * NHEAD + h) * NSEQ * NSEQ;
        int nrow0 = blockIdx.x * 128 + rb + g;
        biasR0 = bb + (size_t)nrow0 * NSEQ;
        biasR1 = bb + (size_t)(nrow0 + 8) * NSEQ;
    }

    float m0 = -1e30f, m1 = -1e30f, l0 = 0.0f, l1 = 0.0f;
    float oacc[4][4];
    #pragma unroll
    for (int ni = 0; ni < 4; ++ni)
        #pragma unroll
        for (int r = 0; r < 4; ++r) oacc[ni][r] = 0.0f;

    for (int jt = 0; jt < 32; ++jt) {
        // ---- stage K (transposed) + V tiles (32 x 32 each) ----
        {
            int r = tid >> 3, c4 = tid & 7;
            float4 kk = *(const float4*)(Km + (size_t)(kvb + jt * 32 + r) * DIMM + h * 32 + c4 * 4);
            KsT[c4 * 4 + 0][r] = tf32_of(kk.x);
            KsT[c4 * 4 + 1][r] = tf32_of(kk.y);
            KsT[c4 * 4 + 2][r] = tf32_of(kk.z);
            KsT[c4 * 4 + 3][r] = tf32_of(kk.w);
            float4 vv = *(const float4*)(Vm + (size_t)(kvb + jt * 32 + r) * DIMM + h * 32 + c4 * 4);
            Vs[r][c4 * 4 + 0] = tf32_of(vv.x);
            Vs[r][c4 * 4 + 1] = tf32_of(vv.y);
            Vs[r][c4 * 4 + 2] = tf32_of(vv.z);
            Vs[r][c4 * 4 + 3] = tf32_of(vv.w);
        }
        __syncthreads();

        // ---- S = Q K^T : rows rb..rb+15, cols 0..31 ----
        float sacc[4][4];
        #pragma unroll
        for (int ni = 0; ni < 4; ++ni)
            #pragma unroll
            for (int r = 0; r < 4; ++r) sacc[ni][r] = 0.0f;
        #pragma unroll
        for (int k8 = 0; k8 < 4; ++k8) {
            int ko = k8 * 8;
            uint32_t a0 = Qs[rb + g    ][ko + t];
            uint32_t a1 = Qs[rb + 8 + g][ko + t];
            uint32_t a2 = Qs[rb + g    ][ko + t + 4];
            uint32_t a3 = Qs[rb + 8 + g][ko + t + 4];
            #pragma unroll
            for (int ni = 0; ni < 4; ++ni) {
                uint32_t b0 = KsT[ko + t    ][ni * 8 + g];
                uint32_t b1 = KsT[ko + t + 4][ni * 8 + g];
                mma_tf32(sacc[ni][0], sacc[ni][1], sacc[ni][2], sacc[ni][3],
                         a0, a1, a2, a3, b0, b1);
            }
        }

        // ---- scale + bias ----
        #pragma unroll
        for (int ni = 0; ni < 4; ++ni) {
            if (HASBIAS) {
                int mcol = jt * 32 + ni * 8 + 2 * t;
                float2 bv0 = __ldg((const float2*)(biasR0 + mcol));
                float2 bv1 = __ldg((const float2*)(biasR1 + mcol));
                sacc[ni][0] = sacc[ni][0] * ATT_SCALE + bv0.x;
                sacc[ni][1] = sacc[ni][1] * ATT_SCALE + bv0.y;
                sacc[ni][2] = sacc[ni][2] * ATT_SCALE + bv1.x;
                sacc[ni][3] = sacc[ni][3] * ATT_SCALE + bv1.y;
            } else {
                sacc[ni][0] *= ATT_SCALE; sacc[ni][1] *= ATT_SCALE;
                sacc[ni][2] *= ATT_SCALE; sacc[ni][3] *= ATT_SCALE;
            }
        }

        // ---- running softmax (state in registers; quad shuffles) ----
        float mx0 = -1e30f, mx1 = -1e30f;
        #pragma unroll
        for (int ni = 0; ni < 4; ++ni) {
            mx0 = fmaxf(mx0, fmaxf(sacc[ni][0], sacc[ni][1]));
            mx1 = fmaxf(mx1, fmaxf(sacc[ni][2], sacc[ni][3]));
        }
        mx0 = fmaxf(mx0, __shfl_xor_sync(0xFFFFFFFFu, mx0, 1));
        mx0 = fmaxf(mx0, __shfl_xor_sync(0xFFFFFFFFu, mx0, 2));
        mx1 = fmaxf(mx1, __shfl_xor_sync(0xFFFFFFFFu, mx1, 1));
        mx1 = fmaxf(mx1, __shfl_xor_sync(0xFFFFFFFFu, mx1, 2));

        float nm0 = fmaxf(m0, mx0), nm1 = fmaxf(m1, mx1);
        float al0 = __expf(m0 - nm0), al1 = __expf(m1 - nm1);
        float sum0 = 0.0f, sum1 = 0.0f;
        #pragma unroll
        for (int ni = 0; ni < 4; ++ni) {
            float p00 = __expf(sacc[ni][0] - nm0);
            float p01 = __expf(sacc[ni][1] - nm0);
            float p10 = __expf(sacc[ni][2] - nm1);
            float p11 = __expf(sacc[ni][3] - nm1);
            sum0 += p00 + p01;
            sum1 += p10 + p11;
            int mc = ni * 8 + 2 * t;
            Ps[rb + g    ][mc    ] = tf32_of(p00);
            Ps[rb + g    ][mc + 1] = tf32_of(p01);
            Ps[rb + 8 + g][mc    ] = tf32_of(p10);
            Ps[rb + 8 + g][mc + 1] = tf32_of(p11);
        }
        sum0 += __shfl_xor_sync(0xFFFFFFFFu, sum0, 1);
        sum0 += __shfl_xor_sync(0xFFFFFFFFu, sum0, 2);
        sum1 += __shfl_xor_sync(0xFFFFFFFFu, sum1, 1);
        sum1 += __shfl_xor_sync(0xFFFFFFFFu, sum1, 2);
        l0 = l0 * al0 + sum0;  m0 = nm0;
        l1 = l1 * al1 + sum1;  m1 = nm1;

        // rescale O accumulators
        #pragma unroll
        for (int ni = 0; ni < 4; ++ni) {
            oacc[ni][0] *= al0; oacc[ni][1] *= al0;
            oacc[ni][2] *= al1; oacc[ni][3] *= al1;
        }
        __syncthreads();

        // ---- O += P V : k = m (32), n = d (32) ----
        #pragma unroll
        for (int k8 = 0; k8 < 4; ++k8) {
            int ko = k8 * 8;
            uint32_t a0 = Ps[rb + g    ][ko + t];
            uint32_t a1 = Ps[rb + 8 + g][ko + t];
            uint32_t a2 = Ps[rb + g    ][ko + t + 4];
            uint32_t a3 = Ps[rb + 8 + g][ko + t + 4];
            #pragma unroll
            for (int ni = 0; ni < 4; ++ni) {
                uint32_t b0 = Vs[ko + t    ][ni * 8 + g];
                uint32_t b1 = Vs[ko + t + 4][ni * 8 + g];
                mma_tf32(oacc[ni][0], oacc[ni][1], oacc[ni][2], oacc[ni][3],
                         a0, a1, a2, a3, b0, b1);
            }
        }
        __syncthreads();
    }

    // ---- normalize + store ----
    float inv0 = 1.0f / l0, inv1 = 1.0f / l1;
    int r0 = qb + rb + g, r1 = r0 + 8;
    #pragma unroll
    for (int ni = 0; ni < 4; ++ni) {
        int col = h * 32 + ni * 8 + 2 * t;
        *(float2*)(O + (size_t)r0 * DIMM + col) =
            make_float2(oacc[ni][0] * inv0, oacc[ni][1] * inv0);
        *(float2*)(O + (size_t)r1 * DIMM + col) =
            make_float2(oacc[ni][2] * inv1, oacc[ni][3] * inv1);
    }
}

// ---------------------------------------------------------------------------
// Host orchestration
// ---------------------------------------------------------------------------
extern "C" void kernel_launch(void* const* d_in, const int* in_sizes, int n_in,
                              void* d_out, int out_size)
{
    (void)in_sizes; (void)n_in; (void)out_size;

    const float* src   = (const float*)d_in[0];
    const float* tgt   = (const float*)d_in[1];
    const float* biasS = (const float*)d_in[2];
    const float* biasT = (const float*)d_in[3];
    // 4..11: sa q_w,q_b,k_w,k_b,v_w,v_b,o_w,o_b ; 12..19: ca same
    // 20..25: ln_sa_g, ln_sa_b, ln_ca_g, ln_ca_b, ln_ff_g, ln_ff_b
    // 26..29: ffn_w1, ffn_b1, ffn_w2, ffn_b2
    #define IN(i) ((const float*)d_in[(i)])

    float *xn, *q, *k, *v, *att, *hbuf;
    cudaGetSymbolAddress((void**)&xn,   g_xn);
    cudaGetSymbolAddress((void**)&q,    g_q);
    cudaGetSymbolAddress((void**)&k,    g_k);
    cudaGetSymbolAddress((void**)&v,    g_v);
    cudaGetSymbolAddress((void**)&att,  g_att);
    cudaGetSymbolAddress((void**)&hbuf, g_h);

    float* cur = (float*)d_out;     // running residual; stream 0 then stream 1
    size_t half = (size_t)4096 * DIMM * sizeof(float);
    cudaMemcpyAsync(cur, src, half, cudaMemcpyDeviceToDevice);
    cudaMemcpyAsync(cur + (size_t)4096 * DIMM, tgt, half, cudaMemcpyDeviceToDevice);

    dim3 gProj(4, 64);      // Nc=256 GEMMs over 8192 tokens
    dim3 gFfn1(16, 64);     // Nc=1024
    dim3 gFlash(8, 64);     // 128-row q-tiles x (s,b,h)

    // ---- stage 1: geometric self-attention (pre-norm residual) ----
    ln_kernel<<<TOKS, 256>>>(cur, IN(20), IN(21), xn);
    gemm_kernel<256, false, false><<<gProj, 256>>>(xn, IN(4),  IN(5),  q, 256);
    gemm_kernel<256, false, false><<<gProj, 256>>>(xn, IN(6),  IN(7),  k, 256);
    gemm_kernel<256, false, false><<<gProj, 256>>>(xn, IN(8),  IN(9),  v, 256);
    flash_kernel<true><<<gFlash, 256>>>(q, k, v, biasS, biasT, att, 0);
    gemm_kernel<256, false, true><<<gProj, 256>>>(att, IN(10), IN(11), cur, 256);

    // ---- stage 2: cross-attention (kv from the other stream) ----
    ln_kernel<<<TOKS, 256>>>(cur, IN(22), IN(23), xn);
    gemm_kernel<256, false, false><<<gProj, 256>>>(xn, IN(12), IN(13), q, 256);
    gemm_kernel<256, false, false><<<gProj, 256>>>(xn, IN(14), IN(15), k, 256);
    gemm_kernel<256, false, false><<<gProj, 256>>>(xn, IN(16), IN(17), v, 256);
    flash_kernel<false><<<gFlash, 256>>>(q, k, v, nullptr, nullptr, att, 1);
    gemm_kernel<256, false, true><<<gProj, 256>>>(att, IN(18), IN(19), cur, 256);

    // ---- stage 3: FFN ----
    ln_kernel<<<TOKS, 256>>>(cur, IN(24), IN(25), xn);
    gemm_kernel<256,  true,  false><<<gFfn1, 256>>>(xn,   IN(26), IN(27), hbuf, 1024);
    gemm_kernel<1024, false, true ><<<gProj, 256>>>(hbuf, IN(28), IN(29), cur,  256);

    #undef IN
}

// round 14
// speedup vs baseline: 3.3619x; 1.1760x over previous
#include <cuda_runtime.h>
#include <math.h>
#include <stddef.h>
#include <stdint.h>

// ---------------------------------------------------------------------------
// GeometricCrossAttentionBlock — pipelined tf32 GEMMs + tf32 flash attention
//   streams: 0 = src (tokens 0..4095), 1 = tgt (tokens 4096..8191)
//   d_out doubles as the running residual buffer "cur" [8192][256]
// ---------------------------------------------------------------------------

#define TOKS   8192
#define DIMM   256
#define NSEQ   1024
#define NHEAD  8
#define HDIM   32
#define FFND   1024
#define ATT_SCALE 0.17677669529663687f   /* 32^-0.5 */

// -------------------- device scratch (allocation-free rule) ----------------
__device__ float g_xn [TOKS * DIMM];            //  8 MB   LN output
__device__ float g_q  [TOKS * DIMM];            //  8 MB
__device__ float g_k  [TOKS * DIMM];            //  8 MB
__device__ float g_v  [TOKS * DIMM];            //  8 MB
__device__ float g_att[TOKS * DIMM];            //  8 MB   attention out (pre O-proj)
__device__ float g_h  [TOKS * FFND];            // 32 MB   FFN hidden

// -------------------- tf32 helpers -----------------------------------------
__device__ __forceinline__ uint32_t tf32_of(float x) {
    uint32_t r; asm("cvt.rna.tf32.f32 %0, %1;" : "=r"(r) : "f"(x)); return r;
}
__device__ __forceinline__ void mma_tf32(
    float& d0, float& d1, float& d2, float& d3,
    uint32_t a0, uint32_t a1, uint32_t a2, uint32_t a3,
    uint32_t b0, uint32_t b1)
{
    asm volatile(
        "mma.sync.aligned.m16n8k8.row.col.f32.tf32.tf32.f32 "
        "{%0,%1,%2,%3}, {%4,%5,%6,%7}, {%8,%9}, {%0,%1,%2,%3};"
        : "+f"(d0), "+f"(d1), "+f"(d2), "+f"(d3)
        : "r"(a0), "r"(a1), "r"(a2), "r"(a3), "r"(b0), "r"(b1));
}

// ---------------------------------------------------------------------------
// LayerNorm over last dim (256). One block (256 thr) per row.
// ---------------------------------------------------------------------------
__global__ void __launch_bounds__(256) ln_kernel(
    const float* __restrict__ in, const float* __restrict__ g,
    const float* __restrict__ b, float* __restrict__ out)
{
    int t = blockIdx.x;
    int c = threadIdx.x;
    float x = in[(size_t)t * DIMM + c];
    float s = x, sq = x * x;
    #pragma unroll
    for (int o = 16; o; o >>= 1) {
        s  += __shfl_xor_sync(0xFFFFFFFFu, s,  o);
        sq += __shfl_xor_sync(0xFFFFFFFFu, sq, o);
    }
    __shared__ float sh1[8], sh2[8];
    int w = c >> 5, l = c & 31;
    if (l == 0) { sh1[w] = s; sh2[w] = sq; }
    __syncthreads();
    if (w == 0) {
        s = sh1[l & 7]; sq = sh2[l & 7];
        #pragma unroll
        for (int o = 4; o; o >>= 1) {
            s  += __shfl_xor_sync(0xFFFFFFFFu, s,  o);
            sq += __shfl_xor_sync(0xFFFFFFFFu, sq, o);
        }
        if (l == 0) { sh1[0] = s; sh2[0] = sq; }
    }
    __syncthreads();
    float mean = sh1[0] * (1.0f / DIMM);
    float var  = sh2[0] * (1.0f / DIMM) - mean * mean;
    float rstd = rsqrtf(var + 1e-5f);
    out[(size_t)t * DIMM + c] = (x - mean) * rstd * g[c] + b[c];
}

// ---------------------------------------------------------------------------
// Pipelined tf32 GEMM core: C[128x64 tile] = A[. x K] @ W[K x Nc] + bias
//   Double-buffered smem, register prefetch. 8 warps (4m x 2n), 32x32/warp.
// ---------------------------------------------------------------------------
template<int K, bool DOGELU, bool RES>
__device__ __forceinline__ void gemm_core(
    const float* __restrict__ A, const float* __restrict__ W,
    const float* __restrict__ bias, float* __restrict__ C, int Nc,
    int m0, int n0,
    uint32_t (*As)[128][20], uint32_t (*Ws)[16][72])
{
    int tid  = threadIdx.x;
    int lane = tid & 31, warp = tid >> 5;
    int wm = warp >> 1, wn = warp & 1;
    int g = lane >> 2, t = lane & 3;

    // staging coordinates
    int sr = tid >> 2;            // A row 0..63 (and +64)
    int sc = (tid & 3) * 4;       // A col 0,4,8,12
    int wr = tid >> 4;            // W row 0..15
    int wc = (tid & 15) * 4;      // W col 0..60

    const int KT = K / 16;
    float4 ra0, ra1, rw;

    // prologue: load + stage chunk 0
    ra0 = *(const float4*)(A + (size_t)(m0 + sr)      * K + sc);
    ra1 = *(const float4*)(A + (size_t)(m0 + sr + 64) * K + sc);
    rw  = *(const float4*)(W + (size_t)wr * Nc + n0 + wc);
    As[0][sr     ][sc + 0] = tf32_of(ra0.x);
    As[0][sr     ][sc + 1] = tf32_of(ra0.y);
    As[0][sr     ][sc + 2] = tf32_of(ra0.z);
    As[0][sr     ][sc + 3] = tf32_of(ra0.w);
    As[0][sr + 64][sc + 0] = tf32_of(ra1.x);
    As[0][sr + 64][sc + 1] = tf32_of(ra1.y);
    As[0][sr + 64][sc + 2] = tf32_of(ra1.z);
    As[0][sr + 64][sc + 3] = tf32_of(ra1.w);
    Ws[0][wr][wc + 0] = tf32_of(rw.x);
    Ws[0][wr][wc + 1] = tf32_of(rw.y);
    Ws[0][wr][wc + 2] = tf32_of(rw.z);
    Ws[0][wr][wc + 3] = tf32_of(rw.w);
    __syncthreads();

    float acc[2][4][4];
    #pragma unroll
    for (int mi = 0; mi < 2; ++mi)
        #pragma unroll
        for (int ni = 0; ni < 4; ++ni)
            #pragma unroll
            for (int r = 0; r < 4; ++r) acc[mi][ni][r] = 0.0f;

    for (int kt = 0; kt < KT; ++kt) {
        int buf = kt & 1;
        if (kt + 1 < KT) {                       // prefetch next chunk to regs
            int k0 = (kt + 1) * 16;
            ra0 = *(const float4*)(A + (size_t)(m0 + sr)      * K + k0 + sc);
            ra1 = *(const float4*)(A + (size_t)(m0 + sr + 64) * K + k0 + sc);
            rw  = *(const float4*)(W + (size_t)(k0 + wr) * Nc + n0 + wc);
        }

        #pragma unroll
        for (int ks = 0; ks < 2; ++ks) {
            int ko = ks * 8;
            uint32_t af[2][4];
            #pragma unroll
            for (int mi = 0; mi < 2; ++mi) {
                int rb = wm * 32 + mi * 16 + g;
                af[mi][0] = As[buf][rb    ][ko + t];
                af[mi][1] = As[buf][rb + 8][ko + t];
                af[mi][2] = As[buf][rb    ][ko + t + 4];
                af[mi][3] = As[buf][rb + 8][ko + t + 4];
            }
            #pragma unroll
            for (int ni = 0; ni < 4; ++ni) {
                int cb = wn * 32 + ni * 8 + g;
                uint32_t b0 = Ws[buf][ko + t    ][cb];
                uint32_t b1 = Ws[buf][ko + t + 4][cb];
                #pragma unroll
                for (int mi = 0; mi < 2; ++mi)
                    mma_tf32(acc[mi][ni][0], acc[mi][ni][1],
                             acc[mi][ni][2], acc[mi][ni][3],
                             af[mi][0], af[mi][1], af[mi][2], af[mi][3],
                             b0, b1);
            }
        }

        if (kt + 1 < KT) {                       // stage into alternate buffer
            int nb = buf ^ 1;
            As[nb][sr     ][sc + 0] = tf32_of(ra0.x);
            As[nb][sr     ][sc + 1] = tf32_of(ra0.y);
            As[nb][sr     ][sc + 2] = tf32_of(ra0.z);
            As[nb][sr     ][sc + 3] = tf32_of(ra0.w);
            As[nb][sr + 64][sc + 0] = tf32_of(ra1.x);
            As[nb][sr + 64][sc + 1] = tf32_of(ra1.y);
            As[nb][sr + 64][sc + 2] = tf32_of(ra1.z);
            As[nb][sr + 64][sc + 3] = tf32_of(ra1.w);
            Ws[nb][wr][wc + 0] = tf32_of(rw.x);
            Ws[nb][wr][wc + 1] = tf32_of(rw.y);
            Ws[nb][wr][wc + 2] = tf32_of(rw.z);
            Ws[nb][wr][wc + 3] = tf32_of(rw.w);
            __syncthreads();
        }
    }

    // ---- epilogue ----
    #pragma unroll
    for (int mi = 0; mi < 2; ++mi) {
        int rlo = m0 + wm * 32 + mi * 16 + g;
        int rhi = rlo + 8;
        #pragma unroll
        for (int ni = 0; ni < 4; ++ni) {
            int col = n0 + wn * 32 + ni * 8 + t * 2;
            float2 bv = *(const float2*)(bias + col);
            float v0 = acc[mi][ni][0] + bv.x;
            float v1 = acc[mi][ni][1] + bv.y;
            float v2 = acc[mi][ni][2] + bv.x;
            float v3 = acc[mi][ni][3] + bv.y;
            if (DOGELU) {
                v0 = 0.5f * v0 * (1.0f + erff(v0 * 0.70710678118654752f));
                v1 = 0.5f * v1 * (1.0f + erff(v1 * 0.70710678118654752f));
                v2 = 0.5f * v2 * (1.0f + erff(v2 * 0.70710678118654752f));
                v3 = 0.5f * v3 * (1.0f + erff(v3 * 0.70710678118654752f));
            }
            size_t ilo = (size_t)rlo * Nc + col;
            size_t ihi = (size_t)rhi * Nc + col;
            if (RES) {
                float2 c0 = *(float2*)(C + ilo);
                float2 c1 = *(float2*)(C + ihi);
                v0 += c0.x; v1 += c0.y; v2 += c1.x; v3 += c1.y;
            }
            *(float2*)(C + ilo) = make_float2(v0, v1);
            *(float2*)(C + ihi) = make_float2(v2, v3);
        }
    }
}

template<int K, bool DOGELU, bool RES>
__global__ void __launch_bounds__(256) gemm_kernel(
    const float* __restrict__ A, const float* __restrict__ W,
    const float* __restrict__ bias, float* __restrict__ C, int Nc)
{
    __shared__ uint32_t As[2][128][20];
    __shared__ uint32_t Ws[2][16][72];
    gemm_core<K, DOGELU, RES>(A, W, bias, C, Nc,
                              blockIdx.y * 128, blockIdx.x * 64, As, Ws);
}

// Fused QKV projection: grid (12, 64); blockIdx.x = which*4 + n-tile.
__global__ void __launch_bounds__(256) qkv_kernel(
    const float* __restrict__ A,
    const float* __restrict__ Wq, const float* __restrict__ bq, float* __restrict__ Cq,
    const float* __restrict__ Wk, const float* __restrict__ bk, float* __restrict__ Ck,
    const float* __restrict__ Wv, const float* __restrict__ bv, float* __restrict__ Cv)
{
    __shared__ uint32_t As[2][128][20];
    __shared__ uint32_t Ws[2][16][72];
    int which = blockIdx.x >> 2;
    int n0 = (blockIdx.x & 3) * 64;
    const float* W = (which == 0) ? Wq : (which == 1) ? Wk : Wv;
    const float* b = (which == 0) ? bq : (which == 1) ? bk : bv;
    float*       C = (which == 0) ? Cq : (which == 1) ? Ck : Cv;
    gemm_core<256, false, false>(A, W, b, C, 256, blockIdx.y * 128, n0, As, Ws);
}

// ---------------------------------------------------------------------------
// Flash attention (tf32 mma): one block = (z, 128-row q-tile).
//   8 warps x 16 q-rows; kv-tiles of 32; softmax state in registers.
//   Register prefetch of next K/V tile; warp-local P tile (syncwarp only).
// ---------------------------------------------------------------------------
template<bool HASBIAS>
__global__ void __launch_bounds__(256) flash_kernel(
    const float* __restrict__ Qm, const float* __restrict__ Km,
    const float* __restrict__ Vm,
    const float* __restrict__ biasS, const float* __restrict__ biasT,
    float* __restrict__ O, int kv_swap)
{
    __shared__ uint32_t Qs [128][36];   // [row][d]    tf32
    __shared__ uint32_t KsT[32][36];    // [d][m]      tf32
    __shared__ uint32_t Vs [32][36];    // [m][d]      tf32
    __shared__ uint32_t Ps [128][36];   // [row][m]    tf32

    int tid = threadIdx.x, lane = tid & 31, warp = tid >> 5;
    int g = lane >> 2, t = lane & 3;
    int z = blockIdx.y;
    int s = z >> 5, b = (z >> 3) & 3, h = z & 7;
    int qb = s * 4096 + b * 1024 + blockIdx.x * 128;
    int ksel = kv_swap ? (1 - s) : s;
    int kvb = ksel * 4096 + b * 1024;
    int rb = warp * 16;

    // staging coords for K/V tiles (32 x 32)
    int svr = tid >> 3, svc = (tid & 7) * 4;

    // ---- stage Q tile (128 x 32) ----
    #pragma unroll
    for (int p = 0; p < 4; ++p) {
        int idx = tid + p * 256;
        int r = idx >> 3, c4 = idx & 7;
        float4 a = *(const float4*)(Qm + (size_t)(qb + r) * DIMM + h * 32 + c4 * 4);
        Qs[r][c4 * 4 + 0] = tf32_of(a.x);
        Qs[r][c4 * 4 + 1] = tf32_of(a.y);
        Qs[r][c4 * 4 + 2] = tf32_of(a.z);
        Qs[r][c4 * 4 + 3] = tf32_of(a.w);
    }

    // ---- stage first K/V tile ----
    {
        float4 kk = *(const float4*)(Km + (size_t)(kvb + svr) * DIMM + h * 32 + svc);
        KsT[svc + 0][svr] = tf32_of(kk.x);
        KsT[svc + 1][svr] = tf32_of(kk.y);
        KsT[svc + 2][svr] = tf32_of(kk.z);
        KsT[svc + 3][svr] = tf32_of(kk.w);
        float4 vv = *(const float4*)(Vm + (size_t)(kvb + svr) * DIMM + h * 32 + svc);
        Vs[svr][svc + 0] = tf32_of(vv.x);
        Vs[svr][svc + 1] = tf32_of(vv.y);
        Vs[svr][svc + 2] = tf32_of(vv.z);
        Vs[svr][svc + 3] = tf32_of(vv.w);
    }

    const float* biasR0 = nullptr;
    const float* biasR1 = nullptr;
    if (HASBIAS) {
        const float* bb = ((s == 0) ? biasS : biasT)
                        + (size_t)(b * NHEAD + h) * NSEQ * NSEQ;
        int nrow0 = blockIdx.x * 128 + rb + g;
        biasR0 = bb + (size_t)nrow0 * NSEQ;
        biasR1 = bb + (size_t)(nrow0 + 8) * NSEQ;
    }

    float m0 = -1e30f, m1 = -1e30f, l0 = 0.0f, l1 = 0.0f;
    float oacc[4][4];
    #pragma unroll
    for (int ni = 0; ni < 4; ++ni)
        #pragma unroll
        for (int r = 0; r < 4; ++r) oacc[ni][r] = 0.0f;

    __syncthreads();

    float4 nk, nv;
    for (int jt = 0; jt < 32; ++jt) {
        if (jt + 1 < 32) {    // prefetch next K/V tile into registers
            nk = *(const float4*)(Km + (size_t)(kvb + (jt + 1) * 32 + svr) * DIMM + h * 32 + svc);
            nv = *(const float4*)(Vm + (size_t)(kvb + (jt + 1) * 32 + svr) * DIMM + h * 32 + svc);
        }

        // ---- S = Q K^T : rows rb..rb+15, cols 0..31 ----
        float sacc[4][4];
        #pragma unroll
        for (int ni = 0; ni < 4; ++ni)
            #pragma unroll
            for (int r = 0; r < 4; ++r) sacc[ni][r] = 0.0f;
        #pragma unroll
        for (int k8 = 0; k8 < 4; ++k8) {
            int ko = k8 * 8;
            uint32_t a0 = Qs[rb + g    ][ko + t];
            uint32_t a1 = Qs[rb + 8 + g][ko + t];
            uint32_t a2 = Qs[rb + g    ][ko + t + 4];
            uint32_t a3 = Qs[rb + 8 + g][ko + t + 4];
            #pragma unroll
            for (int ni = 0; ni < 4; ++ni) {
                uint32_t b0 = KsT[ko + t    ][ni * 8 + g];
                uint32_t b1 = KsT[ko + t + 4][ni * 8 + g];
                mma_tf32(sacc[ni][0], sacc[ni][1], sacc[ni][2], sacc[ni][3],
                         a0, a1, a2, a3, b0, b1);
            }
        }

        // ---- scale + bias ----
        #pragma unroll
        for (int ni = 0; ni < 4; ++ni) {
            if (HASBIAS) {
                int mcol = jt * 32 + ni * 8 + 2 * t;
                float2 bv0 = __ldg((const float2*)(biasR0 + mcol));
                float2 bv1 = __ldg((const float2*)(biasR1 + mcol));
                sacc[ni][0] = sacc[ni][0] * ATT_SCALE + bv0.x;
                sacc[ni][1] = sacc[ni][1] * ATT_SCALE + bv0.y;
                sacc[ni][2] = sacc[ni][2] * ATT_SCALE + bv1.x;
                sacc[ni][3] = sacc[ni][3] * ATT_SCALE + bv1.y;
            } else {
                sacc[ni][0] *= ATT_SCALE; sacc[ni][1] *= ATT_SCALE;
                sacc[ni][2] *= ATT_SCALE; sacc[ni][3] *= ATT_SCALE;
            }
        }

        // ---- running softmax (register state; quad shuffles) ----
        float mx0 = -1e30f, mx1 = -1e30f;
        #pragma unroll
        for (int ni = 0; ni < 4; ++ni) {
            mx0 = fmaxf(mx0, fmaxf(sacc[ni][0], sacc[ni][1]));
            mx1 = fmaxf(mx1, fmaxf(sacc[ni][2], sacc[ni][3]));
        }
        mx0 = fmaxf(mx0, __shfl_xor_sync(0xFFFFFFFFu, mx0, 1));
        mx0 = fmaxf(mx0, __shfl_xor_sync(0xFFFFFFFFu, mx0, 2));
        mx1 = fmaxf(mx1, __shfl_xor_sync(0xFFFFFFFFu, mx1, 1));
        mx1 = fmaxf(mx1, __shfl_xor_sync(0xFFFFFFFFu, mx1, 2));

        float nm0 = fmaxf(m0, mx0), nm1 = fmaxf(m1, mx1);
        float al0 = __expf(m0 - nm0), al1 = __expf(m1 - nm1);
        float sum0 = 0.0f, sum1 = 0.0f;
        #pragma unroll
        for (int ni = 0; ni < 4; ++ni) {
            float p00 = __expf(sacc[ni][0] - nm0);
            float p01 = __expf(sacc[ni][1] - nm0);
            float p10 = __expf(sacc[ni][2] - nm1);
            float p11 = __expf(sacc[ni][3] - nm1);
            sum0 += p00 + p01;
            sum1 += p10 + p11;
            int mc = ni * 8 + 2 * t;
            Ps[rb + g    ][mc    ] = tf32_of(p00);
            Ps[rb + g    ][mc + 1] = tf32_of(p01);
            Ps[rb + 8 + g][mc    ] = tf32_of(p10);
            Ps[rb + 8 + g][mc + 1] = tf32_of(p11);
        }
        sum0 += __shfl_xor_sync(0xFFFFFFFFu, sum0, 1);
        sum0 += __shfl_xor_sync(0xFFFFFFFFu, sum0, 2);
        sum1 += __shfl_xor_sync(0xFFFFFFFFu, sum1, 1);
        sum1 += __shfl_xor_sync(0xFFFFFFFFu, sum1, 2);
        l0 = l0 * al0 + sum0;  m0 = nm0;
        l1 = l1 * al1 + sum1;  m1 = nm1;

        #pragma unroll
        for (int ni = 0; ni < 4; ++ni) {
            oacc[ni][0] *= al0; oacc[ni][1] *= al0;
            oacc[ni][2] *= al1; oacc[ni][3] *= al1;
        }
        // P tile is produced and consumed entirely within this warp's rows
        __syncwarp();

        // ---- O += P V ----
        #pragma unroll
        for (int k8 = 0; k8 < 4; ++k8) {
            int ko = k8 * 8;
            uint32_t a0 = Ps[rb + g    ][ko + t];
            uint32_t a1 = Ps[rb + 8 + g][ko + t];
            uint32_t a2 = Ps[rb + g    ][ko + t + 4];
            uint32_t a3 = Ps[rb + 8 + g][ko + t + 4];
            #pragma unroll
            for (int ni = 0; ni < 4; ++ni) {
                uint32_t b0 = Vs[ko + t    ][ni * 8 + g];
                uint32_t b1 = Vs[ko + t + 4][ni * 8 + g];
                mma_tf32(oacc[ni][0], oacc[ni][1], oacc[ni][2], oacc[ni][3],
                         a0, a1, a2, a3, b0, b1);
            }
        }

        if (jt + 1 < 32) {   // stage prefetched K/V (single buffer, post-use)
            __syncthreads();
            KsT[svc + 0][svr] = tf32_of(nk.x);
            KsT[svc + 1][svr] = tf32_of(nk.y);
            KsT[svc + 2][svr] = tf32_of(nk.z);
            KsT[svc + 3][svr] = tf32_of(nk.w);
            Vs[svr][svc + 0] = tf32_of(nv.x);
            Vs[svr][svc + 1] = tf32_of(nv.y);
            Vs[svr][svc + 2] = tf32_of(nv.z);
            Vs[svr][svc + 3] = tf32_of(nv.w);
            __syncthreads();
        }
    }

    // ---- normalize + store ----
    float inv0 = 1.0f / l0, inv1 = 1.0f / l1;
    int r0 = qb + rb + g, r1 = r0 + 8;
    #pragma unroll
    for (int ni = 0; ni < 4; ++ni) {
        int col = h * 32 + ni * 8 + 2 * t;
        *(float2*)(O + (size_t)r0 * DIMM + col) =
            make_float2(oacc[ni][0] * inv0, oacc[ni][1] * inv0);
        *(float2*)(O + (size_t)r1 * DIMM + col) =
            make_float2(oacc[ni][2] * inv1, oacc[ni][3] * inv1);
    }
}

// ---------------------------------------------------------------------------
// Host orchestration
// ---------------------------------------------------------------------------
extern "C" void kernel_launch(void* const* d_in, const int* in_sizes, int n_in,
                              void* d_out, int out_size)
{
    (void)in_sizes; (void)n_in; (void)out_size;

    const float* src   = (const float*)d_in[0];
    const float* tgt   = (const float*)d_in[1];
    const float* biasS = (const float*)d_in[2];
    const float* biasT = (const float*)d_in[3];
    // 4..11: sa q_w,q_b,k_w,k_b,v_w,v_b,o_w,o_b ; 12..19: ca same
    // 20..25: ln_sa_g, ln_sa_b, ln_ca_g, ln_ca_b, ln_ff_g, ln_ff_b
    // 26..29: ffn_w1, ffn_b1, ffn_w2, ffn_b2
    #define IN(i) ((const float*)d_in[(i)])

    float *xn, *q, *k, *v, *att, *hbuf;
    cudaGetSymbolAddress((void**)&xn,   g_xn);
    cudaGetSymbolAddress((void**)&q,    g_q);
    cudaGetSymbolAddress((void**)&k,    g_k);
    cudaGetSymbolAddress((void**)&v,    g_v);
    cudaGetSymbolAddress((void**)&att,  g_att);
    cudaGetSymbolAddress((void**)&hbuf, g_h);

    float* cur = (float*)d_out;     // running residual; stream 0 then stream 1
    size_t half = (size_t)4096 * DIMM * sizeof(float);
    cudaMemcpyAsync(cur, src, half, cudaMemcpyDeviceToDevice);
    cudaMemcpyAsync(cur + (size_t)4096 * DIMM, tgt, half, cudaMemcpyDeviceToDevice);

    dim3 gProj(4, 64);      // Nc=256 GEMMs over 8192 tokens
    dim3 gQkv(12, 64);      // fused QKV
    dim3 gFfn1(16, 64);     // Nc=1024
    dim3 gFlash(8, 64);     // 128-row q-tiles x (s,b,h)

    // ---- stage 1: geometric self-attention (pre-norm residual) ----
    ln_kernel<<<TOKS, 256>>>(cur, IN(20), IN(21), xn);
    qkv_kernel<<<gQkv, 256>>>(xn, IN(4), IN(5), q, IN(6), IN(7), k, IN(8), IN(9), v);
    flash_kernel<true><<<gFlash, 256>>>(q, k, v, biasS, biasT, att, 0);
    gemm_kernel<256, false, true><<<gProj, 256>>>(att, IN(10), IN(11), cur, 256);

    // ---- stage 2: cross-attention (kv from the other stream) ----
    ln_kernel<<<TOKS, 256>>>(cur, IN(22), IN(23), xn);
    qkv_kernel<<<gQkv, 256>>>(xn, IN(12), IN(13), q, IN(14), IN(15), k, IN(16), IN(17), v);
    flash_kernel<false><<<gFlash, 256>>>(q, k, v, nullptr, nullptr, att, 1);
    gemm_kernel<256, false, true><<<gProj, 256>>>(att, IN(18), IN(19), cur, 256);

    // ---- stage 3: FFN ----
    ln_kernel<<<TOKS, 256>>>(cur, IN(24), IN(25), xn);
    gemm_kernel<256,  true,  false><<<gFfn1, 256>>>(xn,   IN(26), IN(27), hbuf, 1024);
    gemm_kernel<1024, false, true ><<<gProj, 256>>>(hbuf, IN(28), IN(29), cur,  256);

    #undef IN
}

// round 17
// speedup vs baseline: 3.6990x; 1.1002x over previous
#include <cuda_runtime.h>
#include <math.h>
#include <stddef.h>
#include <stdint.h>

// ---------------------------------------------------------------------------
// GeometricCrossAttentionBlock — cp.async tf32 GEMMs + tf32 flash attention
//   streams: 0 = src (tokens 0..4095), 1 = tgt (tokens 4096..8191)
//   d_out doubles as the running residual buffer "cur" [8192][256]
//   NOTE: mma.tf32 ignores low mantissa bits -> raw fp32 operands are valid.
// ---------------------------------------------------------------------------

#define TOKS   8192
#define DIMM   256
#define NSEQ   1024
#define NHEAD  8
#define HDIM   32
#define FFND   1024
#define ATT_SCALE 0.17677669529663687f   /* 32^-0.5 */

// -------------------- device scratch (allocation-free rule) ----------------
__device__ float g_xn [TOKS * DIMM];            //  8 MB   LN output
__device__ float g_q  [TOKS * DIMM];            //  8 MB
__device__ float g_k  [TOKS * DIMM];            //  8 MB
__device__ float g_v  [TOKS * DIMM];            //  8 MB
__device__ float g_att[TOKS * DIMM];            //  8 MB   attention out (pre O-proj)
__device__ float g_h  [TOKS * FFND];            // 32 MB   FFN hidden

// -------------------- mma / cp.async helpers --------------------------------
__device__ __forceinline__ void mma_tf32(
    float& d0, float& d1, float& d2, float& d3,
    uint32_t a0, uint32_t a1, uint32_t a2, uint32_t a3,
    uint32_t b0, uint32_t b1)
{
    asm volatile(
        "mma.sync.aligned.m16n8k8.row.col.f32.tf32.tf32.f32 "
        "{%0,%1,%2,%3}, {%4,%5,%6,%7}, {%8,%9}, {%0,%1,%2,%3};"
        : "+f"(d0), "+f"(d1), "+f"(d2), "+f"(d3)
        : "r"(a0), "r"(a1), "r"(a2), "r"(a3), "r"(b0), "r"(b1));
}
__device__ __forceinline__ void cp_async16(void* smem, const void* gmem) {
    uint32_t s = (uint32_t)__cvta_generic_to_shared(smem);
    asm volatile("cp.async.cg.shared.global [%0], [%1], 16;" :: "r"(s), "l"(gmem));
}
__device__ __forceinline__ void cp_commit() {
    asm volatile("cp.async.commit_group;");
}
__device__ __forceinline__ void cp_wait_all() {
    asm volatile("cp.async.wait_group 0;");
}
__device__ __forceinline__ uint32_t fbits(float x) { return __float_as_uint(x); }

// ---------------------------------------------------------------------------
// LayerNorm over last dim (256). One block (256 thr) per row.
// ---------------------------------------------------------------------------
__global__ void __launch_bounds__(256) ln_kernel(
    const float* __restrict__ in, const float* __restrict__ g,
    const float* __restrict__ b, float* __restrict__ out)
{
    int t = blockIdx.x;
    int c = threadIdx.x;
    float x = in[(size_t)t * DIMM + c];
    float s = x, sq = x * x;
    #pragma unroll
    for (int o = 16; o; o >>= 1) {
        s  += __shfl_xor_sync(0xFFFFFFFFu, s,  o);
        sq += __shfl_xor_sync(0xFFFFFFFFu, sq, o);
    }
    __shared__ float sh1[8], sh2[8];
    int w = c >> 5, l = c & 31;
    if (l == 0) { sh1[w] = s; sh2[w] = sq; }
    __syncthreads();
    if (w == 0) {
        s = sh1[l & 7]; sq = sh2[l & 7];
        #pragma unroll
        for (int o = 4; o; o >>= 1) {
            s  += __shfl_xor_sync(0xFFFFFFFFu, s,  o);
            sq += __shfl_xor_sync(0xFFFFFFFFu, sq, o);
        }
        if (l == 0) { sh1[0] = s; sh2[0] = sq; }
    }
    __syncthreads();
    float mean = sh1[0] * (1.0f / DIMM);
    float var  = sh2[0] * (1.0f / DIMM) - mean * mean;
    float rstd = rsqrtf(var + 1e-5f);
    out[(size_t)t * DIMM + c] = (x - mean) * rstd * g[c] + b[c];
}

// ---------------------------------------------------------------------------
// cp.async tf32 GEMM core: C[64x64 tile] = A[. x K] @ W[K x Nc] + bias
//   128 threads, 4 warps as 2(m) x 2(n), warp tile 32x32, K-chunk 16,
//   double-buffered smem, raw-fp32 operands (tf32 truncation in HW).
// ---------------------------------------------------------------------------
template<int K, bool DOGELU, bool RES>
__device__ __forceinline__ void gemm_core(
    const float* __restrict__ A, const float* __restrict__ W,
    const float* __restrict__ bias, float* __restrict__ C, int Nc,
    int m0, int n0,
    float (*As)[64][20], float (*Ws)[16][72])
{
    int tid  = threadIdx.x;
    int lane = tid & 31, warp = tid >> 5;
    int wm = warp >> 1, wn = warp & 1;
    int g = lane >> 2, t = lane & 3;

    // staging coords (float4 granularity, 2 chunks each of A and W per thread)
    int ar0 = tid >> 2,            ac0 = (tid & 3) * 4;          // A idx p=0
    int ar1 = (tid + 128) >> 2,    ac1 = ac0;                    // A idx p=1
    int wr0 = tid >> 4,            wc0 = (tid & 15) * 4;         // W idx p=0
    int wr1 = (tid + 128) >> 4,    wc1 = wc0;                    // W idx p=1

    const int KT = K / 16;

    // prologue: stage chunk 0
    cp_async16(&As[0][ar0][ac0], A + (size_t)(m0 + ar0) * K + ac0);
    cp_async16(&As[0][ar1][ac1], A + (size_t)(m0 + ar1) * K + ac1);
    cp_async16(&Ws[0][wr0][wc0], W + (size_t)wr0 * Nc + n0 + wc0);
    cp_async16(&Ws[0][wr1][wc1], W + (size_t)wr1 * Nc + n0 + wc1);
    cp_commit();

    float acc[2][4][4];
    #pragma unroll
    for (int mi = 0; mi < 2; ++mi)
        #pragma unroll
        for (int ni = 0; ni < 4; ++ni)
            #pragma unroll
            for (int r = 0; r < 4; ++r) acc[mi][ni][r] = 0.0f;

    for (int kt = 0; kt < KT; ++kt) {
        int buf = kt & 1;
        cp_wait_all();
        __syncthreads();
        if (kt + 1 < KT) {                  // stage next chunk into alt buffer
            int k0 = (kt + 1) * 16, nb = buf ^ 1;
            cp_async16(&As[nb][ar0][ac0], A + (size_t)(m0 + ar0) * K + k0 + ac0);
            cp_async16(&As[nb][ar1][ac1], A + (size_t)(m0 + ar1) * K + k0 + ac1);
            cp_async16(&Ws[nb][wr0][wc0], W + (size_t)(k0 + wr0) * Nc + n0 + wc0);
            cp_async16(&Ws[nb][wr1][wc1], W + (size_t)(k0 + wr1) * Nc + n0 + wc1);
            cp_commit();
        }

        #pragma unroll
        for (int ks = 0; ks < 2; ++ks) {
            int ko = ks * 8;
            uint32_t af[2][4];
            #pragma unroll
            for (int mi = 0; mi < 2; ++mi) {
                int rb = wm * 32 + mi * 16 + g;
                af[mi][0] = fbits(As[buf][rb    ][ko + t]);
                af[mi][1] = fbits(As[buf][rb + 8][ko + t]);
                af[mi][2] = fbits(As[buf][rb    ][ko + t + 4]);
                af[mi][3] = fbits(As[buf][rb + 8][ko + t + 4]);
            }
            #pragma unroll
            for (int ni = 0; ni < 4; ++ni) {
                int cb = wn * 32 + ni * 8 + g;
                uint32_t b0 = fbits(Ws[buf][ko + t    ][cb]);
                uint32_t b1 = fbits(Ws[buf][ko + t + 4][cb]);
                #pragma unroll
                for (int mi = 0; mi < 2; ++mi)
                    mma_tf32(acc[mi][ni][0], acc[mi][ni][1],
                             acc[mi][ni][2], acc[mi][ni][3],
                             af[mi][0], af[mi][1], af[mi][2], af[mi][3],
                             b0, b1);
            }
        }
    }

    // ---- epilogue: bias (+GELU) (+residual) ----
    #pragma unroll
    for (int mi = 0; mi < 2; ++mi) {
        int rlo = m0 + wm * 32 + mi * 16 + g;
        int rhi = rlo + 8;
        #pragma unroll
        for (int ni = 0; ni < 4; ++ni) {
            int col = n0 + wn * 32 + ni * 8 + t * 2;
            float2 bv = *(const float2*)(bias + col);
            float v0 = acc[mi][ni][0] + bv.x;
            float v1 = acc[mi][ni][1] + bv.y;
            float v2 = acc[mi][ni][2] + bv.x;
            float v3 = acc[mi][ni][3] + bv.y;
            if (DOGELU) {
                v0 = 0.5f * v0 * (1.0f + erff(v0 * 0.70710678118654752f));
                v1 = 0.5f * v1 * (1.0f + erff(v1 * 0.70710678118654752f));
                v2 = 0.5f * v2 * (1.0f + erff(v2 * 0.70710678118654752f));
                v3 = 0.5f * v3 * (1.0f + erff(v3 * 0.70710678118654752f));
            }
            size_t ilo = (size_t)rlo * Nc + col;
            size_t ihi = (size_t)rhi * Nc + col;
            if (RES) {
                float2 c0 = *(float2*)(C + ilo);
                float2 c1 = *(float2*)(C + ihi);
                v0 += c0.x; v1 += c0.y; v2 += c1.x; v3 += c1.y;
            }
            *(float2*)(C + ilo) = make_float2(v0, v1);
            *(float2*)(C + ihi) = make_float2(v2, v3);
        }
    }
}

template<int K, bool DOGELU, bool RES>
__global__ void __launch_bounds__(128) gemm_kernel(
    const float* __restrict__ A, const float* __restrict__ W,
    const float* __restrict__ bias, float* __restrict__ C, int Nc)
{
    __shared__ float As[2][64][20];
    __shared__ float Ws[2][16][72];
    gemm_core<K, DOGELU, RES>(A, W, bias, C, Nc,
                              blockIdx.y * 64, blockIdx.x * 64, As, Ws);
}

// Fused QKV projection: grid (12, 128); blockIdx.x = which*4 + n-tile.
__global__ void __launch_bounds__(128) qkv_kernel(
    const float* __restrict__ A,
    const float* __restrict__ Wq, const float* __restrict__ bq, float* __restrict__ Cq,
    const float* __restrict__ Wk, const float* __restrict__ bk, float* __restrict__ Ck,
    const float* __restrict__ Wv, const float* __restrict__ bv, float* __restrict__ Cv)
{
    __shared__ float As[2][64][20];
    __shared__ float Ws[2][16][72];
    int which = blockIdx.x >> 2;
    int n0 = (blockIdx.x & 3) * 64;
    const float* W = (which == 0) ? Wq : (which == 1) ? Wk : Wv;
    const float* b = (which == 0) ? bq : (which == 1) ? bk : bv;
    float*       C = (which == 0) ? Cq : (which == 1) ? Ck : Cv;
    gemm_core<256, false, false>(A, W, b, C, 256, blockIdx.y * 64, n0, As, Ws);
}

// ---------------------------------------------------------------------------
// Flash attention (tf32 mma, raw-fp32 operands): one block = (z, 128-row q-tile).
//   8 warps x 16 q-rows; kv-tiles of 32; softmax state in registers.
// ---------------------------------------------------------------------------
template<bool HASBIAS>
__global__ void __launch_bounds__(256) flash_kernel(
    const float* __restrict__ Qm, const float* __restrict__ Km,
    const float* __restrict__ Vm,
    const float* __restrict__ biasS, const float* __restrict__ biasT,
    float* __restrict__ O, int kv_swap)
{
    __shared__ float Qs[128][36];   // [row][d]
    __shared__ float Ks[32][36];    // [m][d]   (B operand, col-major view)
    __shared__ float Vs[32][36];    // [m][d]
    __shared__ float Ps[128][36];   // [row][m]

    int tid = threadIdx.x, lane = tid & 31, warp = tid >> 5;
    int g = lane >> 2, t = lane & 3;
    int z = blockIdx.y;
    int s = z >> 5, b = (z >> 3) & 3, h = z & 7;
    int qb = s * 4096 + b * 1024 + blockIdx.x * 128;
    int ksel = kv_swap ? (1 - s) : s;
    int kvb = ksel * 4096 + b * 1024;
    int rb = warp * 16;

    int svr = tid >> 3, svc = (tid & 7) * 4;   // K/V staging coords

    // ---- stage Q tile (128 x 32) ----
    #pragma unroll
    for (int p = 0; p < 4; ++p) {
        int idx = tid + p * 256;
        int r = idx >> 3, c4 = (idx & 7) * 4;
        *(float4*)&Qs[r][c4] =
            *(const float4*)(Qm + (size_t)(qb + r) * DIMM + h * 32 + c4);
    }
    // ---- stage first K/V tile ----
    *(float4*)&Ks[svr][svc] =
        *(const float4*)(Km + (size_t)(kvb + svr) * DIMM + h * 32 + svc);
    *(float4*)&Vs[svr][svc] =
        *(const float4*)(Vm + (size_t)(kvb + svr) * DIMM + h * 32 + svc);

    const float* biasR0 = nullptr;
    const float* biasR1 = nullptr;
    if (HASBIAS) {
        const float* bb = ((s == 0) ? biasS : biasT)
                        + (size_t)(b * NHEAD + h) * NSEQ * NSEQ;
        int nrow0 = blockIdx.x * 128 + rb + g;
        biasR0 = bb + (size_t)nrow0 * NSEQ;
        biasR1 = bb + (size_t)(nrow0 + 8) * NSEQ;
    }

    float m0 = -1e30f, m1 = -1e30f, l0 = 0.0f, l1 = 0.0f;
    float oacc[4][4];
    #pragma unroll
    for (int ni = 0; ni < 4; ++ni)
        #pragma unroll
        for (int r = 0; r < 4; ++r) oacc[ni][r] = 0.0f;

    __syncthreads();

    float4 nk, nv;
    for (int jt = 0; jt < 32; ++jt) {
        if (jt + 1 < 32) {    // prefetch next K/V tile into registers
            nk = *(const float4*)(Km + (size_t)(kvb + (jt + 1) * 32 + svr) * DIMM + h * 32 + svc);
            nv = *(const float4*)(Vm + (size_t)(kvb + (jt + 1) * 32 + svr) * DIMM + h * 32 + svc);
        }

        // ---- S = Q K^T : rows rb..rb+15, cols 0..31 ----
        float sacc[4][4];
        #pragma unroll
        for (int ni = 0; ni < 4; ++ni)
            #pragma unroll
            for (int r = 0; r < 4; ++r) sacc[ni][r] = 0.0f;
        #pragma unroll
        for (int k8 = 0; k8 < 4; ++k8) {
            int ko = k8 * 8;
            uint32_t a0 = fbits(Qs[rb + g    ][ko + t]);
            uint32_t a1 = fbits(Qs[rb + 8 + g][ko + t]);
            uint32_t a2 = fbits(Qs[rb + g    ][ko + t + 4]);
            uint32_t a3 = fbits(Qs[rb + 8 + g][ko + t + 4]);
            #pragma unroll
            for (int ni = 0; ni < 4; ++ni) {
                uint32_t b0 = fbits(Ks[ni * 8 + g][ko + t    ]);
                uint32_t b1 = fbits(Ks[ni * 8 + g][ko + t + 4]);
                mma_tf32(sacc[ni][0], sacc[ni][1], sacc[ni][2], sacc[ni][3],
                         a0, a1, a2, a3, b0, b1);
            }
        }

        // ---- scale + bias ----
        #pragma unroll
        for (int ni = 0; ni < 4; ++ni) {
            if (HASBIAS) {
                int mcol = jt * 32 + ni * 8 + 2 * t;
                float2 bv0 = __ldg((const float2*)(biasR0 + mcol));
                float2 bv1 = __ldg((const float2*)(biasR1 + mcol));
                sacc[ni][0] = sacc[ni][0] * ATT_SCALE + bv0.x;
                sacc[ni][1] = sacc[ni][1] * ATT_SCALE + bv0.y;
                sacc[ni][2] = sacc[ni][2] * ATT_SCALE + bv1.x;
                sacc[ni][3] = sacc[ni][3] * ATT_SCALE + bv1.y;
            } else {
                sacc[ni][0] *= ATT_SCALE; sacc[ni][1] *= ATT_SCALE;
                sacc[ni][2] *= ATT_SCALE; sacc[ni][3] *= ATT_SCALE;
            }
        }

        // ---- running softmax (register state; quad shuffles) ----
        float mx0 = -1e30f, mx1 = -1e30f;
        #pragma unroll
        for (int ni = 0; ni < 4; ++ni) {
            mx0 = fmaxf(mx0, fmaxf(sacc[ni][0], sacc[ni][1]));
            mx1 = fmaxf(mx1, fmaxf(sacc[ni][2], sacc[ni][3]));
        }
        mx0 = fmaxf(mx0, __shfl_xor_sync(0xFFFFFFFFu, mx0, 1));
        mx0 = fmaxf(mx0, __shfl_xor_sync(0xFFFFFFFFu, mx0, 2));
        mx1 = fmaxf(mx1, __shfl_xor_sync(0xFFFFFFFFu, mx1, 1));
        mx1 = fmaxf(mx1, __shfl_xor_sync(0xFFFFFFFFu, mx1, 2));

        float nm0 = fmaxf(m0, mx0), nm1 = fmaxf(m1, mx1);
        float al0 = __expf(m0 - nm0), al1 = __expf(m1 - nm1);
        float sum0 = 0.0f, sum1 = 0.0f;
        #pragma unroll
        for (int ni = 0; ni < 4; ++ni) {
            float p00 = __expf(sacc[ni][0] - nm0);
            float p01 = __expf(sacc[ni][1] - nm0);
            float p10 = __expf(sacc[ni][2] - nm1);
            float p11 = __expf(sacc[ni][3] - nm1);
            sum0 += p00 + p01;
            sum1 += p10 + p11;
            int mc = ni * 8 + 2 * t;
            Ps[rb + g    ][mc    ] = p00;
            Ps[rb + g    ][mc + 1] = p01;
            Ps[rb + 8 + g][mc    ] = p10;
            Ps[rb + 8 + g][mc + 1] = p11;
        }
        sum0 += __shfl_xor_sync(0xFFFFFFFFu, sum0, 1);
        sum0 += __shfl_xor_sync(0xFFFFFFFFu, sum0, 2);
        sum1 += __shfl_xor_sync(0xFFFFFFFFu, sum1, 1);
        sum1 += __shfl_xor_sync(0xFFFFFFFFu, sum1, 2);
        l0 = l0 * al0 + sum0;  m0 = nm0;
        l1 = l1 * al1 + sum1;  m1 = nm1;

        #pragma unroll
        for (int ni = 0; ni < 4; ++ni) {
            oacc[ni][0] *= al0; oacc[ni][1] *= al0;
            oacc[ni][2] *= al1; oacc[ni][3] *= al1;
        }
        // P tile produced/consumed within this warp's own 16 rows
        __syncwarp();

        // ---- O += P V ----
        #pragma unroll
        for (int k8 = 0; k8 < 4; ++k8) {
            int ko = k8 * 8;
            uint32_t a0 = fbits(Ps[rb + g    ][ko + t]);
            uint32_t a1 = fbits(Ps[rb + 8 + g][ko + t]);
            uint32_t a2 = fbits(Ps[rb + g    ][ko + t + 4]);
            uint32_t a3 = fbits(Ps[rb + 8 + g][ko + t + 4]);
            #pragma unroll
            for (int ni = 0; ni < 4; ++ni) {
                uint32_t b0 = fbits(Vs[ko + t    ][ni * 8 + g]);
                uint32_t b1 = fbits(Vs[ko + t + 4][ni * 8 + g]);
                mma_tf32(oacc[ni][0], oacc[ni][1], oacc[ni][2], oacc[ni][3],
                         a0, a1, a2, a3, b0, b1);
            }
        }

        if (jt + 1 < 32) {   // stage prefetched K/V (single buffer, post-use)
            __syncthreads();
            *(float4*)&Ks[svr][svc] = nk;
            *(float4*)&Vs[svr][svc] = nv;
            __syncthreads();
        }
    }

    // ---- normalize + store ----
    float inv0 = 1.0f / l0, inv1 = 1.0f / l1;
    int r0 = qb + rb + g, r1 = r0 + 8;
    #pragma unroll
    for (int ni = 0; ni < 4; ++ni) {
        int col = h * 32 + ni * 8 + 2 * t;
        *(float2*)(O + (size_t)r0 * DIMM + col) =
            make_float2(oacc[ni][0] * inv0, oacc[ni][1] * inv0);
        *(float2*)(O + (size_t)r1 * DIMM + col) =
            make_float2(oacc[ni][2] * inv1, oacc[ni][3] * inv1);
    }
}

// ---------------------------------------------------------------------------
// Host orchestration
// ---------------------------------------------------------------------------
extern "C" void kernel_launch(void* const* d_in, const int* in_sizes, int n_in,
                              void* d_out, int out_size)
{
    (void)in_sizes; (void)n_in; (void)out_size;

    const float* src   = (const float*)d_in[0];
    const float* tgt   = (const float*)d_in[1];
    const float* biasS = (const float*)d_in[2];
    const float* biasT = (const float*)d_in[3];
    // 4..11: sa q_w,q_b,k_w,k_b,v_w,v_b,o_w,o_b ; 12..19: ca same
    // 20..25: ln_sa_g, ln_sa_b, ln_ca_g, ln_ca_b, ln_ff_g, ln_ff_b
    // 26..29: ffn_w1, ffn_b1, ffn_w2, ffn_b2
    #define IN(i) ((const float*)d_in[(i)])

    float *xn, *q, *k, *v, *att, *hbuf;
    cudaGetSymbolAddress((void**)&xn,   g_xn);
    cudaGetSymbolAddress((void**)&q,    g_q);
    cudaGetSymbolAddress((void**)&k,    g_k);
    cudaGetSymbolAddress((void**)&v,    g_v);
    cudaGetSymbolAddress((void**)&att,  g_att);
    cudaGetSymbolAddress((void**)&hbuf, g_h);

    float* cur = (float*)d_out;     // running residual; stream 0 then stream 1
    size_t half = (size_t)4096 * DIMM * sizeof(float);
    cudaMemcpyAsync(cur, src, half, cudaMemcpyDeviceToDevice);
    cudaMemcpyAsync(cur + (size_t)4096 * DIMM, tgt, half, cudaMemcpyDeviceToDevice);

    dim3 gProj(4, 128);     // 64x64 tiles, Nc=256
    dim3 gQkv(12, 128);     // fused QKV
    dim3 gFfn1(16, 128);    // Nc=1024
    dim3 gFlash(8, 64);     // 128-row q-tiles x (s,b,h)

    // ---- stage 1: geometric self-attention (pre-norm residual) ----
    ln_kernel<<<TOKS, 256>>>(cur, IN(20), IN(21), xn);
    qkv_kernel<<<gQkv, 128>>>(xn, IN(4), IN(5), q, IN(6), IN(7), k, IN(8), IN(9), v);
    flash_kernel<true><<<gFlash, 256>>>(q, k, v, biasS, biasT, att, 0);
    gemm_kernel<256, false, true><<<gProj, 128>>>(att, IN(10), IN(11), cur, 256);

    // ---- stage 2: cross-attention (kv from the other stream) ----
    ln_kernel<<<TOKS, 256>>>(cur, IN(22), IN(23), xn);
    qkv_kernel<<<gQkv, 128>>>(xn, IN(12), IN(13), q, IN(14), IN(15), k, IN(16), IN(17), v);
    flash_kernel<false><<<gFlash, 256>>>(q, k, v, nullptr, nullptr, att, 1);
    gemm_kernel<256, false, true><<<gProj, 128>>>(att, IN(18), IN(19), cur, 256);

    // ---- stage 3: FFN ----
    ln_kernel<<<TOKS, 256>>>(cur, IN(24), IN(25), xn);
    gemm_kernel<256,  true,  false><<<gFfn1, 128>>>(xn,   IN(26), IN(27), hbuf, 1024);
    gemm_kernel<1024, false, true ><<<gProj, 128>>>(hbuf, IN(28), IN(29), cur,  256);

    #undef IN
}